// round 5
// baseline (speedup 1.0000x reference)
#include <cuda_runtime.h>
#include <cstdint>

// ---------------------------------------------------------------------------
// Problem constants
// ---------------------------------------------------------------------------
#define BB    64
#define CIN   2048
#define COUT  32
#define HH    14
#define WW    14
#define HWHW  196        // 14*14
#define REP   1024
#define K6    (CIN * COUT)   // 65536

#define CONV_KS 8
#define CONV_CPB (CIN / CONV_KS)   // 256 channels per block
#define FC6_KS  32
#define FC7_KS  8

// ---------------------------------------------------------------------------
// Scratch (device globals: allocation-free rule). Kernels reference these
// directly via compile-time template selection; kernel_launch does nothing
// but launch kernels.
// ---------------------------------------------------------------------------
__device__ float g_am_part[CONV_KS * BB * COUT * HWHW]; // conv K-split partials
__device__ float g_am[BB * COUT * HWHW];                // attention map (with bias)
__device__ float g_feat[BB * K6];                       // pooled/196, [b][i*32+o]
__device__ float g_h6p[FC6_KS * BB * REP];              // fc6 partials
__device__ float g_h6[BB * REP];                        // relu(fc6)
__device__ float g_outp[FC7_KS * BB * REP];             // fc7 partials

// ---------------------------------------------------------------------------
// Kernel 1: conv3x3, pad=1. Implicit GEMM, K split over channels.
// Block = (ks, b): all 32 couts x 256 virtual positions (16x16 grid) of
// batch b, accumulating channels [ks*256, (ks+1)*256).
// Thread t: position group pg = t>>3 (8 consecutive x of one row-half),
//           cout group q = t&7  (couts 4q..4q+3).
// Per channel: load padded 18x20 image + 9x32 weights to smem, FMA.
// ---------------------------------------------------------------------------
__global__ void __launch_bounds__(256) conv_partial_kernel(
    const float* __restrict__ x, const float* __restrict__ w) {
    __shared__ float s_x[18 * 20]; // padded channel image (zero halo)
    __shared__ float s_w[9 * 32];  // [tap][cout]

    const int ks = blockIdx.x, b = blockIdx.y;
    const int t = threadIdx.x;

    for (int i = t; i < 18 * 20; i += 256) s_x[i] = 0.f; // halo rows/cols stay 0

    const int pg  = t >> 3;          // 0..31 position groups
    const int q   = t & 7;           // cout group -> couts q*4 .. q*4+3
    const int vy  = pg >> 1;         // 0..15 (valid < 14)
    const int vx0 = (pg & 1) * 8;    // 0 or 8

    float acc[8][4];
#pragma unroll
    for (int i = 0; i < 8; ++i)
#pragma unroll
        for (int j = 0; j < 4; ++j) acc[i][j] = 0.f;

    const float* xb = x + (size_t)b * CIN * HWHW;
    const int c0 = ks * CONV_CPB;
    __syncthreads();

    for (int cc = 0; cc < CONV_CPB; ++cc) {
        const int c = c0 + cc;
        if (t < HWHW) {
            const int iy = t / 14, ix = t - iy * 14;
            s_x[(iy + 1) * 20 + ix + 1] = xb[(size_t)c * HWHW + t];
        }
        for (int i = t; i < 288; i += 256) {          // s_w[k][o]
            const int k = i >> 5, o = i & 31;
            s_w[i] = w[((size_t)o * CIN + c) * 9 + k];
        }
        __syncthreads();

        float win[3][10];
#pragma unroll
        for (int dy = 0; dy < 3; ++dy)
#pragma unroll
            for (int j = 0; j < 10; ++j)
                win[dy][j] = s_x[(vy + dy) * 20 + vx0 + j];

#pragma unroll
        for (int k = 0; k < 9; ++k) {
            const int dy = k / 3, dx = k - dy * 3;
            float wv[4];
#pragma unroll
            for (int j = 0; j < 4; ++j) wv[j] = s_w[k * 32 + q * 4 + j];
#pragma unroll
            for (int i = 0; i < 8; ++i) {
                const float xv = win[dy][dx + i];
#pragma unroll
                for (int j = 0; j < 4; ++j)
                    acc[i][j] = fmaf(xv, wv[j], acc[i][j]);
            }
        }
        __syncthreads();
    }

    if (vy < 14) {
#pragma unroll
        for (int i = 0; i < 8; ++i) {
            const int vx = vx0 + i;
            if (vx < 14) {
                const int p = vy * 14 + vx;
                float* dst = g_am_part + (((size_t)ks * BB + b) * COUT + q * 4) * HWHW + p;
#pragma unroll
                for (int j = 0; j < 4; ++j)
                    dst[(size_t)j * HWHW] = acc[i][j];
            }
        }
    }
}

// Reduce conv K-split partials + conv bias -> g_am[b][o][p]
__global__ void conv_reduce_kernel(const float* __restrict__ cb) {
    const int i = blockIdx.x * 256 + threadIdx.x;
    if (i >= BB * COUT * HWHW) return;
    const int o = (i / HWHW) & (COUT - 1);
    float s = cb[o];
#pragma unroll
    for (int ks = 0; ks < CONV_KS; ++ks)
        s += g_am_part[(size_t)ks * BB * COUT * HWHW + i];
    g_am[i] = s;
}

// ---------------------------------------------------------------------------
// Kernel 2: pooled[b][i][o] = (1/196) sum_p x[b,i,p] * am[b,o,p]
// Per-batch GEMM M=2048 (128/block), N=32, K=196. feat layout [b][i*32+o].
// ---------------------------------------------------------------------------
__global__ void __launch_bounds__(256) einsum_kernel(const float* __restrict__ x) {
    __shared__ float s_xa[128 * 29];
    __shared__ float s_am[32 * 29];

    const int b = blockIdx.y;
    const int i0 = blockIdx.x * 128;
    const int t = threadIdx.x;
    const int im = (t >> 3) * 4;   // 0..124
    const int oq = (t & 7) * 4;    // 0..28

    float acc[4][4] = {};

    const float* xb = x + ((size_t)b * CIN + i0) * HWHW;
    const float* ab = g_am + (size_t)b * COUT * HWHW;

    for (int p0 = 0; p0 < HWHW; p0 += 28) {
        for (int idx = t; idx < 128 * 28; idx += 256) {
            const int ii = idx / 28, pp = idx - ii * 28;
            s_xa[ii * 29 + pp] = xb[(size_t)ii * HWHW + p0 + pp];
        }
        for (int idx = t; idx < 32 * 28; idx += 256) {
            const int oo = idx / 28, pp = idx - oo * 28;
            s_am[oo * 29 + pp] = ab[(size_t)oo * HWHW + p0 + pp];
        }
        __syncthreads();
#pragma unroll 4
        for (int pp = 0; pp < 28; ++pp) {
            float av[4], bv[4];
#pragma unroll
            for (int j = 0; j < 4; ++j) av[j] = s_xa[(im + j) * 29 + pp];
#pragma unroll
            for (int j = 0; j < 4; ++j) bv[j] = s_am[(oq + j) * 29 + pp];
#pragma unroll
            for (int mi = 0; mi < 4; ++mi)
#pragma unroll
                for (int oj = 0; oj < 4; ++oj)
                    acc[mi][oj] = fmaf(av[mi], bv[oj], acc[mi][oj]);
        }
        __syncthreads();
    }

    const float inv = 1.0f / 196.0f;
#pragma unroll
    for (int mi = 0; mi < 4; ++mi)
#pragma unroll
        for (int oj = 0; oj < 4; ++oj)
            g_feat[(size_t)b * K6 + (i0 + im + mi) * COUT + (oq + oj)] =
                acc[mi][oj] * inv;
}

// ---------------------------------------------------------------------------
// Kernel 3/4: C_part[ks][m][n] = sum_{k in chunk} A[m][k] * B[n][k]
// M fixed = 64 (batch). Tile 64x64, K-chunk 32, thread tile 4x4.
// WHICH=0: A=g_feat (K=K6),  part=g_h6p
// WHICH=1: A=g_h6   (K=REP), part=g_outp
// ---------------------------------------------------------------------------
template <int WHICH>
__global__ void __launch_bounds__(256) gemm_nt_partial(
    const float* __restrict__ Bm, int N, int K, int kchunk) {
    __shared__ float sA[32 * 68];
    __shared__ float sB[32 * 68];

    const float* __restrict__ A = (WHICH == 0) ? g_feat : g_h6;
    float* __restrict__ part    = (WHICH == 0) ? g_h6p  : g_outp;

    const int n0 = blockIdx.x * 64;
    const int ks = blockIdx.z;
    const int t = threadIdx.x;
    const int tm = (t >> 4) * 4;   // 0..60
    const int tn = (t & 15) * 4;   // 0..60

    float acc[4][4] = {};

    const int kb0 = ks * kchunk;
    for (int kb = kb0; kb < kb0 + kchunk; kb += 32) {
        for (int i = t; i < 2048; i += 256) {
            const int m = i >> 5, kk = i & 31;
            sA[kk * 68 + m] = A[(size_t)m * K + kb + kk];
        }
        for (int i = t; i < 2048; i += 256) {
            const int n = i >> 5, kk = i & 31;
            sB[kk * 68 + n] = Bm[(size_t)(n0 + n) * K + kb + kk];
        }
        __syncthreads();
#pragma unroll 8
        for (int kk = 0; kk < 32; ++kk) {
            float av[4], bv[4];
#pragma unroll
            for (int j = 0; j < 4; ++j) av[j] = sA[kk * 68 + tm + j];
#pragma unroll
            for (int j = 0; j < 4; ++j) bv[j] = sB[kk * 68 + tn + j];
#pragma unroll
            for (int mi = 0; mi < 4; ++mi)
#pragma unroll
                for (int nj = 0; nj < 4; ++nj)
                    acc[mi][nj] = fmaf(av[mi], bv[nj], acc[mi][nj]);
        }
        __syncthreads();
    }

#pragma unroll
    for (int mi = 0; mi < 4; ++mi)
#pragma unroll
        for (int nj = 0; nj < 4; ++nj)
            part[((size_t)ks * 64 + tm + mi) * N + n0 + tn + nj] = acc[mi][nj];
}

// Reduce K-split partials + bias + relu. MN = 64*1024.
// WHICH=0: part=g_h6p (KS=FC6_KS), out=g_h6.  WHICH=1: part=g_outp, out=arg.
template <int WHICH>
__global__ void fc_reduce_kernel(const float* __restrict__ bias,
                                 float* __restrict__ out_arg) {
    const float* __restrict__ part = (WHICH == 0) ? g_h6p : g_outp;
    float* __restrict__ out        = (WHICH == 0) ? g_h6  : out_arg;
    const int KS                   = (WHICH == 0) ? FC6_KS : FC7_KS;

    const int i = blockIdx.x * 256 + threadIdx.x;
    if (i >= BB * REP) return;
    float s = bias[i & (REP - 1)];
    for (int ks = 0; ks < KS; ++ks)
        s += part[(size_t)ks * BB * REP + i];
    out[i] = fmaxf(s, 0.f);
}

// ---------------------------------------------------------------------------
// Launch: pure kernel launches, nothing else.
// ---------------------------------------------------------------------------
extern "C" void kernel_launch(void* const* d_in, const int* in_sizes, int n_in,
                              void* d_out, int out_size) {
    const float* x  = (const float*)d_in[0];
    const float* cw = (const float*)d_in[1];
    const float* cb = (const float*)d_in[2];
    const float* w6 = (const float*)d_in[3];
    const float* b6 = (const float*)d_in[4];
    const float* w7 = (const float*)d_in[5];
    const float* b7 = (const float*)d_in[6];
    float* out = (float*)d_out;

    conv_partial_kernel<<<dim3(CONV_KS, BB), 256>>>(x, cw);
    conv_reduce_kernel<<<(BB * COUT * HWHW + 255) / 256, 256>>>(cb);
    einsum_kernel<<<dim3(CIN / 128, BB), 256>>>(x);
    gemm_nt_partial<0><<<dim3(REP / 64, 1, FC6_KS), 256>>>(w6, REP, K6, K6 / FC6_KS);
    fc_reduce_kernel<0><<<(BB * REP + 255) / 256, 256>>>(b6, nullptr);
    gemm_nt_partial<1><<<dim3(REP / 64, 1, FC7_KS), 256>>>(w7, REP, REP, REP / FC7_KS);
    fc_reduce_kernel<1><<<(BB * REP + 255) / 256, 256>>>(b7, out);
}

// round 8
// speedup vs baseline: 1.0383x; 1.0383x over previous
#include <cuda_runtime.h>
#include <cuda_bf16.h>
#include <mma.h>
#include <cstdint>

using namespace nvcuda;

// ---------------------------------------------------------------------------
// Problem constants
// ---------------------------------------------------------------------------
#define BB    64
#define CIN   2048
#define COUT  32
#define HH    14
#define WW    14
#define HWHW  196        // 14*14
#define REP   1024
#define K6    (CIN * COUT)   // 65536

#define CONV_KS 8
#define CONV_CPB (CIN / CONV_KS)   // 256 channels per block
#define FC6_KS  32
#define FC6_KCH (K6 / FC6_KS)      // 2048
#define FC7_KS  8

// ---------------------------------------------------------------------------
// Scratch (device globals: allocation-free rule)
// ---------------------------------------------------------------------------
__device__ float g_am_part[CONV_KS * BB * COUT * HWHW]; // conv K-split partials
__device__ float g_am[BB * COUT * HWHW];                // attention map (with bias)
__device__ float g_feat[BB * K6];                       // pooled/196, [b][i*32+o]
__device__ float g_h6p[FC6_KS * BB * REP];              // fc6 partials
__device__ float g_h6[BB * REP];                        // relu(fc6)
__device__ float g_outp[FC7_KS * BB * REP];             // fc7 partials

// ---------------------------------------------------------------------------
// bf16 hi/lo split helper
// ---------------------------------------------------------------------------
__device__ __forceinline__ void split_bf16(float v, __nv_bfloat16& hi, __nv_bfloat16& lo) {
    hi = __float2bfloat16(v);
    lo = __float2bfloat16(v - __bfloat162float(hi));
}

// ---------------------------------------------------------------------------
// Kernel 1: conv3x3, pad=1. Implicit GEMM, K split over channels. (unchanged)
// ---------------------------------------------------------------------------
__global__ void __launch_bounds__(256) conv_partial_kernel(
    const float* __restrict__ x, const float* __restrict__ w) {
    __shared__ float s_x[18 * 20]; // padded channel image (zero halo)
    __shared__ float s_w[9 * 32];  // [tap][cout]

    const int ks = blockIdx.x, b = blockIdx.y;
    const int t = threadIdx.x;

    for (int i = t; i < 18 * 20; i += 256) s_x[i] = 0.f;

    const int pg  = t >> 3;
    const int q   = t & 7;
    const int vy  = pg >> 1;
    const int vx0 = (pg & 1) * 8;

    float acc[8][4];
#pragma unroll
    for (int i = 0; i < 8; ++i)
#pragma unroll
        for (int j = 0; j < 4; ++j) acc[i][j] = 0.f;

    const float* xb = x + (size_t)b * CIN * HWHW;
    const int c0 = ks * CONV_CPB;
    __syncthreads();

    for (int cc = 0; cc < CONV_CPB; ++cc) {
        const int c = c0 + cc;
        if (t < HWHW) {
            const int iy = t / 14, ix = t - iy * 14;
            s_x[(iy + 1) * 20 + ix + 1] = xb[(size_t)c * HWHW + t];
        }
        for (int i = t; i < 288; i += 256) {
            const int k = i >> 5, o = i & 31;
            s_w[i] = w[((size_t)o * CIN + c) * 9 + k];
        }
        __syncthreads();

        float win[3][10];
#pragma unroll
        for (int dy = 0; dy < 3; ++dy)
#pragma unroll
            for (int j = 0; j < 10; ++j)
                win[dy][j] = s_x[(vy + dy) * 20 + vx0 + j];

#pragma unroll
        for (int k = 0; k < 9; ++k) {
            const int dy = k / 3, dx = k - dy * 3;
            float wv[4];
#pragma unroll
            for (int j = 0; j < 4; ++j) wv[j] = s_w[k * 32 + q * 4 + j];
#pragma unroll
            for (int i = 0; i < 8; ++i) {
                const float xv = win[dy][dx + i];
#pragma unroll
                for (int j = 0; j < 4; ++j)
                    acc[i][j] = fmaf(xv, wv[j], acc[i][j]);
            }
        }
        __syncthreads();
    }

    if (vy < 14) {
#pragma unroll
        for (int i = 0; i < 8; ++i) {
            const int vx = vx0 + i;
            if (vx < 14) {
                const int p = vy * 14 + vx;
                float* dst = g_am_part + (((size_t)ks * BB + b) * COUT + q * 4) * HWHW + p;
#pragma unroll
                for (int j = 0; j < 4; ++j)
                    dst[(size_t)j * HWHW] = acc[i][j];
            }
        }
    }
}

__global__ void conv_reduce_kernel(const float* __restrict__ cb) {
    const int i = blockIdx.x * 256 + threadIdx.x;
    if (i >= BB * COUT * HWHW) return;
    const int o = (i / HWHW) & (COUT - 1);
    float s = cb[o];
#pragma unroll
    for (int ks = 0; ks < CONV_KS; ++ks)
        s += g_am_part[(size_t)ks * BB * COUT * HWHW + i];
    g_am[i] = s;
}

// ---------------------------------------------------------------------------
// Kernel 2: einsum -> g_feat (unchanged)
// ---------------------------------------------------------------------------
__global__ void __launch_bounds__(256) einsum_kernel(const float* __restrict__ x) {
    __shared__ float s_xa[128 * 29];
    __shared__ float s_am[32 * 29];

    const int b = blockIdx.y;
    const int i0 = blockIdx.x * 128;
    const int t = threadIdx.x;
    const int im = (t >> 3) * 4;
    const int oq = (t & 7) * 4;

    float acc[4][4] = {};

    const float* xb = x + ((size_t)b * CIN + i0) * HWHW;
    const float* ab = g_am + (size_t)b * COUT * HWHW;

    for (int p0 = 0; p0 < HWHW; p0 += 28) {
        for (int idx = t; idx < 128 * 28; idx += 256) {
            const int ii = idx / 28, pp = idx - ii * 28;
            s_xa[ii * 29 + pp] = xb[(size_t)ii * HWHW + p0 + pp];
        }
        for (int idx = t; idx < 32 * 28; idx += 256) {
            const int oo = idx / 28, pp = idx - oo * 28;
            s_am[oo * 29 + pp] = ab[(size_t)oo * HWHW + p0 + pp];
        }
        __syncthreads();
#pragma unroll 4
        for (int pp = 0; pp < 28; ++pp) {
            float av[4], bv[4];
#pragma unroll
            for (int j = 0; j < 4; ++j) av[j] = s_xa[(im + j) * 29 + pp];
#pragma unroll
            for (int j = 0; j < 4; ++j) bv[j] = s_am[(oq + j) * 29 + pp];
#pragma unroll
            for (int mi = 0; mi < 4; ++mi)
#pragma unroll
                for (int oj = 0; oj < 4; ++oj)
                    acc[mi][oj] = fmaf(av[mi], bv[oj], acc[mi][oj]);
        }
        __syncthreads();
    }

    const float inv = 1.0f / 196.0f;
#pragma unroll
    for (int mi = 0; mi < 4; ++mi)
#pragma unroll
        for (int oj = 0; oj < 4; ++oj)
            g_feat[(size_t)b * K6 + (i0 + im + mi) * COUT + (oq + oj)] =
                acc[mi][oj] * inv;
}

// ---------------------------------------------------------------------------
// Kernel 3 (NEW): fc6 via WMMA bf16 hi/lo split.
// C_part[ks][64][1024] += feat[64, kchunk] @ w6[n, kchunk]^T
// Block: 64(M) x 64(N) tile, K-chunk = 2048, k-step 64.
// 8 warps: warp = (mi = wid>>1 in 0..3, nh = wid&1) -> 2 n-tiles of 16.
// Per k64: load fp32 A/B tiles, split to bf16 hi/lo smem planes,
// 3-combo WMMA accumulation in fp32.
// ---------------------------------------------------------------------------
#define FSTR 72   // padded bf16 row stride

__global__ void __launch_bounds__(256) fc6_wmma_kernel(const float* __restrict__ w6) {
    __shared__ __nv_bfloat16 sA_hi[64 * FSTR];
    __shared__ __nv_bfloat16 sA_lo[64 * FSTR];
    __shared__ __nv_bfloat16 sB_hi[64 * FSTR];
    __shared__ __nv_bfloat16 sB_lo[64 * FSTR];

    const int n0 = blockIdx.x * 64;
    const int ks = blockIdx.y;
    const int t  = threadIdx.x;
    const int wid = t >> 5;
    const int mi  = wid >> 1;      // m-tile 0..3
    const int nh  = wid & 1;       // n-half: n-tiles 2*nh, 2*nh+1

    wmma::fragment<wmma::accumulator, 16, 16, 16, float> c[2];
    wmma::fill_fragment(c[0], 0.0f);
    wmma::fill_fragment(c[1], 0.0f);

    const int row = t >> 2;        // 0..63 (tile row loaded by this thread)
    const int q   = t & 3;         // k-quarter within k64

    const int kb0 = ks * FC6_KCH;
    for (int kb = kb0; kb < kb0 + FC6_KCH; kb += 64) {
        const float* ap = g_feat + (size_t)row * K6 + kb + q * 16;
        const float* bp = w6 + (size_t)(n0 + row) * K6 + kb + q * 16;
#pragma unroll
        for (int j = 0; j < 4; ++j) {
            const float4 av = *(const float4*)(ap + j * 4);
            const float4 bv = *(const float4*)(bp + j * 4);
            const int base = row * FSTR + q * 16 + j * 4;
            split_bf16(av.x, sA_hi[base + 0], sA_lo[base + 0]);
            split_bf16(av.y, sA_hi[base + 1], sA_lo[base + 1]);
            split_bf16(av.z, sA_hi[base + 2], sA_lo[base + 2]);
            split_bf16(av.w, sA_hi[base + 3], sA_lo[base + 3]);
            split_bf16(bv.x, sB_hi[base + 0], sB_lo[base + 0]);
            split_bf16(bv.y, sB_hi[base + 1], sB_lo[base + 1]);
            split_bf16(bv.z, sB_hi[base + 2], sB_lo[base + 2]);
            split_bf16(bv.w, sB_hi[base + 3], sB_lo[base + 3]);
        }
        __syncthreads();

#pragma unroll
        for (int kk = 0; kk < 4; ++kk) {
            wmma::fragment<wmma::matrix_a, 16, 16, 16, __nv_bfloat16, wmma::row_major> a_hi, a_lo;
            wmma::load_matrix_sync(a_hi, sA_hi + (mi * 16) * FSTR + kk * 16, FSTR);
            wmma::load_matrix_sync(a_lo, sA_lo + (mi * 16) * FSTR + kk * 16, FSTR);
#pragma unroll
            for (int nj = 0; nj < 2; ++nj) {
                const int nt = nh * 2 + nj;
                wmma::fragment<wmma::matrix_b, 16, 16, 16, __nv_bfloat16, wmma::col_major> b_hi, b_lo;
                wmma::load_matrix_sync(b_hi, sB_hi + (nt * 16) * FSTR + kk * 16, FSTR);
                wmma::load_matrix_sync(b_lo, sB_lo + (nt * 16) * FSTR + kk * 16, FSTR);
                wmma::mma_sync(c[nj], a_hi, b_hi, c[nj]);
                wmma::mma_sync(c[nj], a_hi, b_lo, c[nj]);
                wmma::mma_sync(c[nj], a_lo, b_hi, c[nj]);
            }
        }
        __syncthreads();
    }

#pragma unroll
    for (int nj = 0; nj < 2; ++nj) {
        float* p = g_h6p + (size_t)ks * BB * REP + (size_t)(mi * 16) * REP
                 + n0 + (nh * 2 + nj) * 16;
        wmma::store_matrix_sync(p, c[nj], REP, wmma::mem_row_major);
    }
}

// ---------------------------------------------------------------------------
// Kernel 4: fp32 K-split GEMM kept for fc7 (small).
// ---------------------------------------------------------------------------
__global__ void __launch_bounds__(256) gemm_nt_partial_fc7(
    const float* __restrict__ Bm, int N, int K, int kchunk) {
    __shared__ float sA[32 * 68];
    __shared__ float sB[32 * 68];

    const float* __restrict__ A = g_h6;
    float* __restrict__ part    = g_outp;

    const int n0 = blockIdx.x * 64;
    const int ks = blockIdx.z;
    const int t = threadIdx.x;
    const int tm = (t >> 4) * 4;
    const int tn = (t & 15) * 4;

    float acc[4][4] = {};

    const int kb0 = ks * kchunk;
    for (int kb = kb0; kb < kb0 + kchunk; kb += 32) {
        for (int i = t; i < 2048; i += 256) {
            const int m = i >> 5, kk = i & 31;
            sA[kk * 68 + m] = A[(size_t)m * K + kb + kk];
        }
        for (int i = t; i < 2048; i += 256) {
            const int n = i >> 5, kk = i & 31;
            sB[kk * 68 + n] = Bm[(size_t)(n0 + n) * K + kb + kk];
        }
        __syncthreads();
#pragma unroll 8
        for (int kk = 0; kk < 32; ++kk) {
            float av[4], bv[4];
#pragma unroll
            for (int j = 0; j < 4; ++j) av[j] = sA[kk * 68 + tm + j];
#pragma unroll
            for (int j = 0; j < 4; ++j) bv[j] = sB[kk * 68 + tn + j];
#pragma unroll
            for (int mi = 0; mi < 4; ++mi)
#pragma unroll
                for (int nj = 0; nj < 4; ++nj)
                    acc[mi][nj] = fmaf(av[mi], bv[nj], acc[mi][nj]);
        }
        __syncthreads();
    }

#pragma unroll
    for (int mi = 0; mi < 4; ++mi)
#pragma unroll
        for (int nj = 0; nj < 4; ++nj)
            part[((size_t)ks * 64 + tm + mi) * N + n0 + tn + nj] = acc[mi][nj];
}

// Reduce K-split partials + bias + relu. MN = 64*1024.
template <int WHICH>
__global__ void fc_reduce_kernel(const float* __restrict__ bias,
                                 float* __restrict__ out_arg) {
    const float* __restrict__ part = (WHICH == 0) ? g_h6p : g_outp;
    float* __restrict__ out        = (WHICH == 0) ? g_h6  : out_arg;
    const int KS                   = (WHICH == 0) ? FC6_KS : FC7_KS;

    const int i = blockIdx.x * 256 + threadIdx.x;
    if (i >= BB * REP) return;
    float s = bias[i & (REP - 1)];
    for (int ks = 0; ks < KS; ++ks)
        s += part[(size_t)ks * BB * REP + i];
    out[i] = fmaxf(s, 0.f);
}

// ---------------------------------------------------------------------------
// Launch: pure kernel launches.
// ---------------------------------------------------------------------------
extern "C" void kernel_launch(void* const* d_in, const int* in_sizes, int n_in,
                              void* d_out, int out_size) {
    const float* x  = (const float*)d_in[0];
    const float* cw = (const float*)d_in[1];
    const float* cb = (const float*)d_in[2];
    const float* w6 = (const float*)d_in[3];
    const float* b6 = (const float*)d_in[4];
    const float* w7 = (const float*)d_in[5];
    const float* b7 = (const float*)d_in[6];
    float* out = (float*)d_out;

    conv_partial_kernel<<<dim3(CONV_KS, BB), 256>>>(x, cw);
    conv_reduce_kernel<<<(BB * COUT * HWHW + 255) / 256, 256>>>(cb);
    einsum_kernel<<<dim3(CIN / 128, BB), 256>>>(x);
    fc6_wmma_kernel<<<dim3(REP / 64, FC6_KS), 256>>>(w6);
    fc_reduce_kernel<0><<<(BB * REP + 255) / 256, 256>>>(b6, nullptr);
    gemm_nt_partial_fc7<<<dim3(REP / 64, 1, FC7_KS), 256>>>(w7, REP, REP, REP / FC7_KS);
    fc_reduce_kernel<1><<<(BB * REP + 255) / 256, 256>>>(b7, out);
}

// round 9
// speedup vs baseline: 2.0633x; 1.9872x over previous
#include <cuda_runtime.h>
#include <cuda_bf16.h>
#include <mma.h>
#include <cstdint>

using namespace nvcuda;

// ---------------------------------------------------------------------------
// Problem constants
// ---------------------------------------------------------------------------
#define BB    64
#define CIN   2048
#define COUT  32
#define HWHW  196        // 14*14
#define REP   1024
#define K6    (CIN * COUT)   // 65536

#define CV_KS  16                 // conv K-split over channels
#define CV_CPB (CIN / CV_KS)      // 128 channels per block
#define CV_CK  16                 // channels per smem step
#define ILD    24                 // image smem ldm (elems, mult of 8, conflict-free)
#define WLD    16                 // weight smem ldm
#define IROWS  272                // padded positions (max read index 257)

#define FC6_KS  64
#define FC6_KCH (K6 / FC6_KS)     // 1024
#define F6_NB   128               // fc6 N per block
#define FSTR    40                // fc6 smem ldm (mult of 8, conflict-free)
#define FC7_KS  8

// ---------------------------------------------------------------------------
// Scratch (device globals: allocation-free rule)
// ---------------------------------------------------------------------------
__device__ float g_am_part[CV_KS * BB * COUT * HWHW];
__device__ float g_am[BB * COUT * HWHW];
__device__ __nv_bfloat16 g_feat_hi[BB * K6];
__device__ __nv_bfloat16 g_feat_lo[BB * K6];
__device__ float g_h6p[FC6_KS * BB * REP];
__device__ float g_h6[BB * REP];
__device__ float g_outp[FC7_KS * BB * REP];

__device__ __forceinline__ void split_bf16(float v, __nv_bfloat16& hi, __nv_bfloat16& lo) {
    hi = __float2bfloat16(v);
    lo = __float2bfloat16(v - __bfloat162float(hi));
}

// ---------------------------------------------------------------------------
// Kernel 1: conv3x3 pad=1 via WMMA bf16 hi/lo, K split over channels.
// Block (ks, b). smem image plane: padded 16x16 positions (halo zero),
// A = image (row-major, tap shift = ptr offset), B = weights (col-major).
// m = y*16 + x; x>=14 columns are garbage, discarded at store.
// ---------------------------------------------------------------------------
__global__ void __launch_bounds__(256) conv_wmma_kernel(
    const float* __restrict__ x, const float* __restrict__ w) {
    __shared__ __align__(16) __nv_bfloat16 sIh[IROWS * ILD];
    __shared__ __align__(16) __nv_bfloat16 sIl[IROWS * ILD];
    __shared__ __align__(16) __nv_bfloat16 sWh[9 * 32 * WLD];
    __shared__ __align__(16) __nv_bfloat16 sWl[9 * 32 * WLD];

    const int ks = blockIdx.x, b = blockIdx.y;
    const int t = threadIdx.x;
    const int wid = t >> 5, lane = t & 31;
    const int mg = wid >> 1;      // m-group: tiles {4mg..4mg+3} (<14)
    const int nt = wid & 1;       // n-tile (16 couts)

    // zero image planes (halo + pad stay zero forever)
    for (int i = t; i < IROWS * ILD; i += 256) { sIh[i] = __float2bfloat16(0.f); sIl[i] = sIh[i]; }

    wmma::fragment<wmma::accumulator, 16, 16, 16, float> c[4];
#pragma unroll
    for (int j = 0; j < 4; ++j) wmma::fill_fragment(c[j], 0.0f);

    __syncthreads();

    const int cbase0 = ks * CV_CPB;
    for (int cc = 0; cc < CV_CPB / CV_CK; ++cc) {
        const int cbase = cbase0 + cc * CV_CK;
        // image: 16 channels x 196 positions
        for (int i = t; i < CV_CK * HWHW; i += 256) {
            const int cl = i / HWHW, p = i - cl * HWHW;
            const int y = p / 14, xx = p - y * 14;
            const float v = x[((size_t)(b * CIN + cbase + cl)) * HWHW + p];
            const int pos = (y + 1) * 16 + (xx + 1);
            split_bf16(v, sIh[pos * ILD + cl], sIl[pos * ILD + cl]);
        }
        // weights: 32 couts x 16 channels x 9 taps
        for (int i = t; i < 32 * CV_CK; i += 256) {
            const int o = i >> 4, cl = i & 15;
            const float* wp = w + ((size_t)o * CIN + cbase + cl) * 9;
#pragma unroll
            for (int tap = 0; tap < 9; ++tap)
                split_bf16(wp[tap], sWh[(tap * 32 + o) * WLD + cl],
                                    sWl[(tap * 32 + o) * WLD + cl]);
        }
        __syncthreads();

#pragma unroll
        for (int tap = 0; tap < 9; ++tap) {
            const int dy = tap / 3, dx = tap - dy * 3;
            const int off = dy * 16 + dx;
            wmma::fragment<wmma::matrix_b, 16, 16, 16, __nv_bfloat16, wmma::col_major> b_hi, b_lo;
            wmma::load_matrix_sync(b_hi, sWh + (tap * 32 + nt * 16) * WLD, WLD);
            wmma::load_matrix_sync(b_lo, sWl + (tap * 32 + nt * 16) * WLD, WLD);
#pragma unroll
            for (int j = 0; j < 4; ++j) {
                const int mt = mg * 4 + j;
                if (mt < 14) {
                    wmma::fragment<wmma::matrix_a, 16, 16, 16, __nv_bfloat16, wmma::row_major> a_hi, a_lo;
                    wmma::load_matrix_sync(a_hi, sIh + (mt * 16 + off) * ILD, ILD);
                    wmma::load_matrix_sync(a_lo, sIl + (mt * 16 + off) * ILD, ILD);
                    wmma::mma_sync(c[j], a_hi, b_hi, c[j]);
                    wmma::mma_sync(c[j], a_hi, b_lo, c[j]);
                    wmma::mma_sync(c[j], a_lo, b_hi, c[j]);
                }
            }
        }
        __syncthreads();
    }

    // store: stage each 16x16 frag in reused smem (sWh region), scatter x<14
    float* stage = reinterpret_cast<float*>(sWh) + wid * 256;
#pragma unroll
    for (int j = 0; j < 4; ++j) {
        const int mt = mg * 4 + j;       // y = mt
        if (mt < 14) {
            wmma::store_matrix_sync(stage, c[j], 16, wmma::mem_row_major);
            __syncwarp();
            for (int e = lane; e < 14 * 16; e += 32) {
                const int row = e >> 4, oc = e & 15;   // row = x (0..13)
                g_am_part[(((size_t)ks * BB + b) * COUT + nt * 16 + oc) * HWHW
                          + mt * 14 + row] = stage[row * 16 + oc];
            }
            __syncwarp();
        }
    }
}

__global__ void conv_reduce_kernel(const float* __restrict__ cb) {
    const int i = blockIdx.x * 256 + threadIdx.x;
    if (i >= BB * COUT * HWHW) return;
    const int o = (i / HWHW) & (COUT - 1);
    float s = cb[o];
#pragma unroll
    for (int ks = 0; ks < CV_KS; ++ks)
        s += g_am_part[(size_t)ks * BB * COUT * HWHW + i];
    g_am[i] = s;
}

// ---------------------------------------------------------------------------
// Kernel 2: einsum -> feat, written directly as bf16 hi/lo planes.
// ---------------------------------------------------------------------------
__global__ void __launch_bounds__(256) einsum_kernel(const float* __restrict__ x) {
    __shared__ float s_xa[128 * 29];
    __shared__ float s_am[32 * 29];

    const int b = blockIdx.y;
    const int i0 = blockIdx.x * 128;
    const int t = threadIdx.x;
    const int im = (t >> 3) * 4;
    const int oq = (t & 7) * 4;

    float acc[4][4] = {};

    const float* xb = x + ((size_t)b * CIN + i0) * HWHW;
    const float* ab = g_am + (size_t)b * COUT * HWHW;

    for (int p0 = 0; p0 < HWHW; p0 += 28) {
        for (int idx = t; idx < 128 * 28; idx += 256) {
            const int ii = idx / 28, pp = idx - ii * 28;
            s_xa[ii * 29 + pp] = xb[(size_t)ii * HWHW + p0 + pp];
        }
        for (int idx = t; idx < 32 * 28; idx += 256) {
            const int oo = idx / 28, pp = idx - oo * 28;
            s_am[oo * 29 + pp] = ab[(size_t)oo * HWHW + p0 + pp];
        }
        __syncthreads();
#pragma unroll 4
        for (int pp = 0; pp < 28; ++pp) {
            float av[4], bv[4];
#pragma unroll
            for (int j = 0; j < 4; ++j) av[j] = s_xa[(im + j) * 29 + pp];
#pragma unroll
            for (int j = 0; j < 4; ++j) bv[j] = s_am[(oq + j) * 29 + pp];
#pragma unroll
            for (int mi = 0; mi < 4; ++mi)
#pragma unroll
                for (int oj = 0; oj < 4; ++oj)
                    acc[mi][oj] = fmaf(av[mi], bv[oj], acc[mi][oj]);
        }
        __syncthreads();
    }

    const float inv = 1.0f / 196.0f;
#pragma unroll
    for (int mi = 0; mi < 4; ++mi)
#pragma unroll
        for (int oj = 0; oj < 4; ++oj) {
            const size_t idx = (size_t)b * K6 + (i0 + im + mi) * COUT + (oq + oj);
            split_bf16(acc[mi][oj] * inv, g_feat_hi[idx], g_feat_lo[idx]);
        }
}

// ---------------------------------------------------------------------------
// Kernel 3: fc6 WMMA. Block: 64M x 128N, K-chunk 1024, k-step 32.
// A = feat (pre-split bf16, direct vector copy), B = w6 (fp32, split here
// with packed uint4 stores). 8 warps, warp tile 32x32.
// ---------------------------------------------------------------------------
__global__ void __launch_bounds__(256) fc6_wmma_kernel(const float* __restrict__ w6) {
    __shared__ __align__(16) __nv_bfloat16 sAh[64 * FSTR];
    __shared__ __align__(16) __nv_bfloat16 sAl[64 * FSTR];
    __shared__ __align__(16) __nv_bfloat16 sBh[128 * FSTR];
    __shared__ __align__(16) __nv_bfloat16 sBl[128 * FSTR];

    const int n0 = blockIdx.x * F6_NB;
    const int ks = blockIdx.y;
    const int t  = threadIdx.x;
    const int wid = t >> 5;
    const int mh  = wid >> 2;      // m-half: tiles {2mh, 2mh+1}
    const int nq  = wid & 3;       // n-quarter: tiles {2nq, 2nq+1}

    wmma::fragment<wmma::accumulator, 16, 16, 16, float> c[2][2];
#pragma unroll
    for (int i = 0; i < 2; ++i)
#pragma unroll
        for (int j = 0; j < 2; ++j) wmma::fill_fragment(c[i][j], 0.0f);

    const int ar = t >> 2, aq = t & 3;   // A: row 0..63, k-eighth
    const int br = t >> 1, bh = t & 1;   // B: row 0..127, k-half

    const int kb0 = ks * FC6_KCH;
    for (int kb = kb0; kb < kb0 + FC6_KCH; kb += 32) {
        // A: copy 8 bf16 per plane per thread (uint4)
        {
            const size_t src = (size_t)ar * K6 + kb + aq * 8;
            const int dst = ar * FSTR + aq * 8;
            *(uint4*)&sAh[dst] = *(const uint4*)&g_feat_hi[src];
            *(uint4*)&sAl[dst] = *(const uint4*)&g_feat_lo[src];
        }
        // B: 16 fp32 per thread -> split -> 2+2 packed uint4 stores
        {
            const float* bp = w6 + (size_t)(n0 + br) * K6 + kb + bh * 16;
            __nv_bfloat16 hi[16], lo[16];
#pragma unroll
            for (int j = 0; j < 4; ++j) {
                const float4 v = *(const float4*)(bp + j * 4);
                split_bf16(v.x, hi[j * 4 + 0], lo[j * 4 + 0]);
                split_bf16(v.y, hi[j * 4 + 1], lo[j * 4 + 1]);
                split_bf16(v.z, hi[j * 4 + 2], lo[j * 4 + 2]);
                split_bf16(v.w, hi[j * 4 + 3], lo[j * 4 + 3]);
            }
            const int dst = br * FSTR + bh * 16;
            *(uint4*)&sBh[dst + 0] = *(const uint4*)&hi[0];
            *(uint4*)&sBh[dst + 8] = *(const uint4*)&hi[8];
            *(uint4*)&sBl[dst + 0] = *(const uint4*)&lo[0];
            *(uint4*)&sBl[dst + 8] = *(const uint4*)&lo[8];
        }
        __syncthreads();

#pragma unroll
        for (int kk = 0; kk < 2; ++kk) {
            wmma::fragment<wmma::matrix_a, 16, 16, 16, __nv_bfloat16, wmma::row_major> a_hi[2], a_lo[2];
#pragma unroll
            for (int i = 0; i < 2; ++i) {
                wmma::load_matrix_sync(a_hi[i], sAh + ((mh * 2 + i) * 16) * FSTR + kk * 16, FSTR);
                wmma::load_matrix_sync(a_lo[i], sAl + ((mh * 2 + i) * 16) * FSTR + kk * 16, FSTR);
            }
#pragma unroll
            for (int j = 0; j < 2; ++j) {
                wmma::fragment<wmma::matrix_b, 16, 16, 16, __nv_bfloat16, wmma::col_major> b_hi, b_lo;
                wmma::load_matrix_sync(b_hi, sBh + ((nq * 2 + j) * 16) * FSTR + kk * 16, FSTR);
                wmma::load_matrix_sync(b_lo, sBl + ((nq * 2 + j) * 16) * FSTR + kk * 16, FSTR);
#pragma unroll
                for (int i = 0; i < 2; ++i) {
                    wmma::mma_sync(c[i][j], a_hi[i], b_hi, c[i][j]);
                    wmma::mma_sync(c[i][j], a_hi[i], b_lo, c[i][j]);
                    wmma::mma_sync(c[i][j], a_lo[i], b_hi, c[i][j]);
                }
            }
        }
        __syncthreads();
    }

#pragma unroll
    for (int i = 0; i < 2; ++i)
#pragma unroll
        for (int j = 0; j < 2; ++j) {
            float* p = g_h6p + (size_t)ks * BB * REP + (size_t)((mh * 2 + i) * 16) * REP
                     + n0 + (nq * 2 + j) * 16;
            wmma::store_matrix_sync(p, c[i][j], REP, wmma::mem_row_major);
        }
}

// ---------------------------------------------------------------------------
// Kernel 4: fp32 K-split GEMM for fc7 (small).
// ---------------------------------------------------------------------------
__global__ void __launch_bounds__(256) gemm_nt_partial_fc7(
    const float* __restrict__ Bm, int N, int K, int kchunk) {
    __shared__ float sA[32 * 68];
    __shared__ float sB[32 * 68];

    const float* __restrict__ A = g_h6;
    float* __restrict__ part    = g_outp;

    const int n0 = blockIdx.x * 64;
    const int ks = blockIdx.z;
    const int t = threadIdx.x;
    const int tm = (t >> 4) * 4;
    const int tn = (t & 15) * 4;

    float acc[4][4] = {};

    const int kb0 = ks * kchunk;
    for (int kb = kb0; kb < kb0 + kchunk; kb += 32) {
        for (int i = t; i < 2048; i += 256) {
            const int m = i >> 5, kk = i & 31;
            sA[kk * 68 + m] = A[(size_t)m * K + kb + kk];
        }
        for (int i = t; i < 2048; i += 256) {
            const int n = i >> 5, kk = i & 31;
            sB[kk * 68 + n] = Bm[(size_t)(n0 + n) * K + kb + kk];
        }
        __syncthreads();
#pragma unroll 8
        for (int kk = 0; kk < 32; ++kk) {
            float av[4], bv[4];
#pragma unroll
            for (int j = 0; j < 4; ++j) av[j] = sA[kk * 68 + tm + j];
#pragma unroll
            for (int j = 0; j < 4; ++j) bv[j] = sB[kk * 68 + tn + j];
#pragma unroll
            for (int mi = 0; mi < 4; ++mi)
#pragma unroll
                for (int nj = 0; nj < 4; ++nj)
                    acc[mi][nj] = fmaf(av[mi], bv[nj], acc[mi][nj]);
        }
        __syncthreads();
    }

#pragma unroll
    for (int mi = 0; mi < 4; ++mi)
#pragma unroll
        for (int nj = 0; nj < 4; ++nj)
            part[((size_t)ks * 64 + tm + mi) * N + n0 + tn + nj] = acc[mi][nj];
}

// Reduce K-split partials + bias + relu.
template <int WHICH>
__global__ void fc_reduce_kernel(const float* __restrict__ bias,
                                 float* __restrict__ out_arg) {
    const float* __restrict__ part = (WHICH == 0) ? g_h6p : g_outp;
    float* __restrict__ out        = (WHICH == 0) ? g_h6  : out_arg;
    const int KS                   = (WHICH == 0) ? FC6_KS : FC7_KS;

    const int i = blockIdx.x * 256 + threadIdx.x;
    if (i >= BB * REP) return;
    float s = bias[i & (REP - 1)];
    for (int ks = 0; ks < KS; ++ks)
        s += part[(size_t)ks * BB * REP + i];
    out[i] = fmaxf(s, 0.f);
}

// ---------------------------------------------------------------------------
// Launch: pure kernel launches.
// ---------------------------------------------------------------------------
extern "C" void kernel_launch(void* const* d_in, const int* in_sizes, int n_in,
                              void* d_out, int out_size) {
    const float* x  = (const float*)d_in[0];
    const float* cw = (const float*)d_in[1];
    const float* cb = (const float*)d_in[2];
    const float* w6 = (const float*)d_in[3];
    const float* b6 = (const float*)d_in[4];
    const float* w7 = (const float*)d_in[5];
    const float* b7 = (const float*)d_in[6];
    float* out = (float*)d_out;

    conv_wmma_kernel<<<dim3(CV_KS, BB), 256>>>(x, cw);
    conv_reduce_kernel<<<(BB * COUT * HWHW + 255) / 256, 256>>>(cb);
    einsum_kernel<<<dim3(CIN / 128, BB), 256>>>(x);
    fc6_wmma_kernel<<<dim3(REP / F6_NB, FC6_KS), 256>>>(w6);
    fc_reduce_kernel<0><<<(BB * REP + 255) / 256, 256>>>(b6, nullptr);
    gemm_nt_partial_fc7<<<dim3(REP / 64, 1, FC7_KS), 256>>>(w7, REP, REP, REP / FC7_KS);
    fc_reduce_kernel<1><<<(BB * REP + 255) / 256, 256>>>(b7, out);
}

// round 10
// speedup vs baseline: 2.2390x; 1.0851x over previous
#include <cuda_runtime.h>
#include <cuda_bf16.h>
#include <mma.h>
#include <cstdint>

using namespace nvcuda;

// ---------------------------------------------------------------------------
// Problem constants
// ---------------------------------------------------------------------------
#define BB    64
#define CIN   2048
#define COUT  32
#define HWHW  196        // 14*14
#define REP   1024
#define K6    (CIN * COUT)   // 65536

#define CV_KS  16                 // conv K-split over channels
#define CV_CPB (CIN / CV_KS)      // 128 channels per block
#define CV_CK  16                 // channels per smem step
#define ILD    24                 // image smem ldm
#define WLD    16                 // weight smem ldm
#define IROWS  272

#define FC6_KS  64
#define FC6_KCH (K6 / FC6_KS)     // 1024
#define F6_NB   128               // fc6 N per block
#define F6STR   24                // fc6 smem ldm (k-step 16 + pad 8)
#define FC7_KS  8

#define ELDK    24                // einsum smem ldm (k-step 16 + pad 8)

// ---------------------------------------------------------------------------
// Scratch (device globals)
// ---------------------------------------------------------------------------
__device__ float g_am_part[CV_KS * BB * COUT * HWHW];
__device__ float g_am[BB * COUT * HWHW];
__device__ __nv_bfloat16 g_feat_hi[BB * K6];
__device__ __nv_bfloat16 g_feat_lo[BB * K6];
__device__ float g_h6p[FC6_KS * BB * REP];
__device__ float g_h6[BB * REP];
__device__ float g_outp[FC7_KS * BB * REP];

__device__ __forceinline__ void split_bf16(float v, __nv_bfloat16& hi, __nv_bfloat16& lo) {
    hi = __float2bfloat16(v);
    lo = __float2bfloat16(v - __bfloat162float(hi));
}

// ---------------------------------------------------------------------------
// Kernel 1: conv3x3 pad=1 via WMMA bf16 hi/lo (unchanged from R9)
// ---------------------------------------------------------------------------
__global__ void __launch_bounds__(256) conv_wmma_kernel(
    const float* __restrict__ x, const float* __restrict__ w) {
    __shared__ __align__(16) __nv_bfloat16 sIh[IROWS * ILD];
    __shared__ __align__(16) __nv_bfloat16 sIl[IROWS * ILD];
    __shared__ __align__(16) __nv_bfloat16 sWh[9 * 32 * WLD];
    __shared__ __align__(16) __nv_bfloat16 sWl[9 * 32 * WLD];

    const int ks = blockIdx.x, b = blockIdx.y;
    const int t = threadIdx.x;
    const int wid = t >> 5, lane = t & 31;
    const int mg = wid >> 1;
    const int nt = wid & 1;

    for (int i = t; i < IROWS * ILD; i += 256) { sIh[i] = __float2bfloat16(0.f); sIl[i] = sIh[i]; }

    wmma::fragment<wmma::accumulator, 16, 16, 16, float> c[4];
#pragma unroll
    for (int j = 0; j < 4; ++j) wmma::fill_fragment(c[j], 0.0f);

    __syncthreads();

    const int cbase0 = ks * CV_CPB;
    for (int cc = 0; cc < CV_CPB / CV_CK; ++cc) {
        const int cbase = cbase0 + cc * CV_CK;
        for (int i = t; i < CV_CK * HWHW; i += 256) {
            const int cl = i / HWHW, p = i - cl * HWHW;
            const int y = p / 14, xx = p - y * 14;
            const float v = x[((size_t)(b * CIN + cbase + cl)) * HWHW + p];
            const int pos = (y + 1) * 16 + (xx + 1);
            split_bf16(v, sIh[pos * ILD + cl], sIl[pos * ILD + cl]);
        }
        for (int i = t; i < 32 * CV_CK; i += 256) {
            const int o = i >> 4, cl = i & 15;
            const float* wp = w + ((size_t)o * CIN + cbase + cl) * 9;
#pragma unroll
            for (int tap = 0; tap < 9; ++tap)
                split_bf16(wp[tap], sWh[(tap * 32 + o) * WLD + cl],
                                    sWl[(tap * 32 + o) * WLD + cl]);
        }
        __syncthreads();

#pragma unroll
        for (int tap = 0; tap < 9; ++tap) {
            const int dy = tap / 3, dx = tap - dy * 3;
            const int off = dy * 16 + dx;
            wmma::fragment<wmma::matrix_b, 16, 16, 16, __nv_bfloat16, wmma::col_major> b_hi, b_lo;
            wmma::load_matrix_sync(b_hi, sWh + (tap * 32 + nt * 16) * WLD, WLD);
            wmma::load_matrix_sync(b_lo, sWl + (tap * 32 + nt * 16) * WLD, WLD);
#pragma unroll
            for (int j = 0; j < 4; ++j) {
                const int mt = mg * 4 + j;
                if (mt < 14) {
                    wmma::fragment<wmma::matrix_a, 16, 16, 16, __nv_bfloat16, wmma::row_major> a_hi, a_lo;
                    wmma::load_matrix_sync(a_hi, sIh + (mt * 16 + off) * ILD, ILD);
                    wmma::load_matrix_sync(a_lo, sIl + (mt * 16 + off) * ILD, ILD);
                    wmma::mma_sync(c[j], a_hi, b_hi, c[j]);
                    wmma::mma_sync(c[j], a_hi, b_lo, c[j]);
                    wmma::mma_sync(c[j], a_lo, b_hi, c[j]);
                }
            }
        }
        __syncthreads();
    }

    float* stage = reinterpret_cast<float*>(sWh) + wid * 256;
#pragma unroll
    for (int j = 0; j < 4; ++j) {
        const int mt = mg * 4 + j;
        if (mt < 14) {
            wmma::store_matrix_sync(stage, c[j], 16, wmma::mem_row_major);
            __syncwarp();
            for (int e = lane; e < 14 * 16; e += 32) {
                const int row = e >> 4, oc = e & 15;
                g_am_part[(((size_t)ks * BB + b) * COUT + nt * 16 + oc) * HWHW
                          + mt * 14 + row] = stage[row * 16 + oc];
            }
            __syncwarp();
        }
    }
}

__global__ void conv_reduce_kernel(const float* __restrict__ cb) {
    const int i = blockIdx.x * 256 + threadIdx.x;
    if (i >= BB * COUT * HWHW) return;
    const int o = (i / HWHW) & (COUT - 1);
    float s = cb[o];
#pragma unroll
    for (int ks = 0; ks < CV_KS; ++ks)
        s += g_am_part[(size_t)ks * BB * COUT * HWHW + i];
    g_am[i] = s;
}

// ---------------------------------------------------------------------------
// Kernel 2 (NEW): einsum via WMMA bf16 hi/lo, double-buffered, 1 sync/iter.
// Block (i0 = bx*128 rows of x, b = by). C[128,32] += x @ am^T, K=196
// in 13 k-steps of 16 (tail zero-padded). Epilogue: *1/196, split, write
// bf16 feat planes.
// ---------------------------------------------------------------------------
__global__ void __launch_bounds__(256) einsum_wmma_kernel(const float* __restrict__ x) {
    __shared__ __align__(16) char esm[30720];
    __nv_bfloat16* sXh  = (__nv_bfloat16*)esm;             // [2][128*24]
    __nv_bfloat16* sXl  = (__nv_bfloat16*)(esm + 12288);   // [2][128*24]
    __nv_bfloat16* sAmh = (__nv_bfloat16*)(esm + 24576);   // [2][32*24]
    __nv_bfloat16* sAml = (__nv_bfloat16*)(esm + 27648);   // [2][32*24]

    const int i0 = blockIdx.x * 128;
    const int b  = blockIdx.y;
    const int t  = threadIdx.x;
    const int wid = t >> 5, lane = t & 31;

    // load mapping
    const int xr = t >> 1, xh = t & 1;      // x: row 0..127, k-half (8 floats)
    const int ao = t >> 3, aq = t & 7;      // am: row 0..31, k-pair (2 floats)

    const float* xb = x + ((size_t)(b * CIN + i0 + xr)) * HWHW;
    const float* ab = g_am + ((size_t)b * COUT + ao) * HWHW;

    float4 xv0, xv1;
    float  av0, av1;

    auto loadS = [&](int s) {
        const int k0 = s * 16 + xh * 8;
        xv0 = (k0     < HWHW) ? *(const float4*)(xb + k0)     : make_float4(0,0,0,0);
        xv1 = (k0 + 4 < HWHW) ? *(const float4*)(xb + k0 + 4) : make_float4(0,0,0,0);
        const int ka = s * 16 + aq * 2;
        av0 = (ka     < HWHW) ? ab[ka]     : 0.f;
        av1 = (ka + 1 < HWHW) ? ab[ka + 1] : 0.f;
    };

    wmma::fragment<wmma::accumulator, 16, 16, 16, float> c[2];
    wmma::fill_fragment(c[0], 0.0f);
    wmma::fill_fragment(c[1], 0.0f);

    loadS(0);
    const int NS = 13;
    for (int s = 0; s < NS; ++s) {
        const int buf = s & 1;
        // split + STS (X: 8 bf16 per plane packed as uint4)
        {
            __nv_bfloat16 hi[8], lo[8];
            split_bf16(xv0.x, hi[0], lo[0]); split_bf16(xv0.y, hi[1], lo[1]);
            split_bf16(xv0.z, hi[2], lo[2]); split_bf16(xv0.w, hi[3], lo[3]);
            split_bf16(xv1.x, hi[4], lo[4]); split_bf16(xv1.y, hi[5], lo[5]);
            split_bf16(xv1.z, hi[6], lo[6]); split_bf16(xv1.w, hi[7], lo[7]);
            const int d = buf * 3072 + xr * ELDK + xh * 8;
            *(uint4*)&sXh[d] = *(const uint4*)&hi[0];
            *(uint4*)&sXl[d] = *(const uint4*)&lo[0];
            __nv_bfloat16 ah0, al0, ah1, al1;
            split_bf16(av0, ah0, al0); split_bf16(av1, ah1, al1);
            const int da = buf * 768 + ao * ELDK + aq * 2;
            sAmh[da] = ah0; sAmh[da + 1] = ah1;
            sAml[da] = al0; sAml[da + 1] = al1;
        }
        if (s + 1 < NS) loadS(s + 1);     // issue next loads before barrier
        __syncthreads();

        wmma::fragment<wmma::matrix_a, 16, 16, 16, __nv_bfloat16, wmma::row_major> a_hi, a_lo;
        wmma::load_matrix_sync(a_hi, sXh + buf * 3072 + (wid * 16) * ELDK, ELDK);
        wmma::load_matrix_sync(a_lo, sXl + buf * 3072 + (wid * 16) * ELDK, ELDK);
#pragma unroll
        for (int j = 0; j < 2; ++j) {
            wmma::fragment<wmma::matrix_b, 16, 16, 16, __nv_bfloat16, wmma::col_major> b_hi, b_lo;
            wmma::load_matrix_sync(b_hi, sAmh + buf * 768 + (j * 16) * ELDK, ELDK);
            wmma::load_matrix_sync(b_lo, sAml + buf * 768 + (j * 16) * ELDK, ELDK);
            wmma::mma_sync(c[j], a_hi, b_hi, c[j]);
            wmma::mma_sync(c[j], a_hi, b_lo, c[j]);
            wmma::mma_sync(c[j], a_lo, b_hi, c[j]);
        }
        // single barrier per iteration (double-buffer makes the 2nd redundant)
    }
    __syncthreads();   // before smem reuse as stage

    // epilogue: stage fp32 16x32 per warp, scale, split, write feat planes
    float* stage = (float*)esm + wid * 512;
    wmma::store_matrix_sync(stage,      c[0], 32, wmma::mem_row_major);
    wmma::store_matrix_sync(stage + 16, c[1], 32, wmma::mem_row_major);
    __syncwarp();
    const float inv = 1.0f / 196.0f;
    for (int r = 0; r < 16; ++r) {
        const float v = stage[r * 32 + lane] * inv;
        const size_t idx = (size_t)b * K6 + (size_t)(i0 + wid * 16 + r) * COUT + lane;
        split_bf16(v, g_feat_hi[idx], g_feat_lo[idx]);
    }
}

// ---------------------------------------------------------------------------
// Kernel 3 (NEW): fc6 WMMA, double-buffered, 1 sync/iter.
// Block: 64M x 128N, K-chunk 1024, k-step 16. 8 warps, warp tile 32x32.
// ---------------------------------------------------------------------------
__global__ void __launch_bounds__(256) fc6_wmma_kernel(const float* __restrict__ w6) {
    __shared__ __align__(16) char fsm[36864];
    __nv_bfloat16* sAh = (__nv_bfloat16*)fsm;               // [2][64*24]
    __nv_bfloat16* sAl = (__nv_bfloat16*)(fsm + 6144);      // [2][64*24]
    __nv_bfloat16* sBh = (__nv_bfloat16*)(fsm + 12288);     // [2][128*24]
    __nv_bfloat16* sBl = (__nv_bfloat16*)(fsm + 24576);     // [2][128*24]

    const int n0 = blockIdx.x * F6_NB;
    const int ks = blockIdx.y;
    const int t  = threadIdx.x;
    const int wid = t >> 5;
    const int mh  = wid >> 2;      // m-half: tiles {2mh, 2mh+1}
    const int nq  = wid & 3;       // n-quarter: tiles {2nq, 2nq+1}

    const int ar = t >> 2, aq = t & 3;   // A: row 0..63, k-quarter (4 bf16)
    const int br = t >> 1, bh2 = t & 1;  // B: row 0..127, k-half (8 fp32)

    const __nv_bfloat16* fh = g_feat_hi + (size_t)ar * K6;
    const __nv_bfloat16* fl = g_feat_lo + (size_t)ar * K6;
    const float* bp0 = w6 + (size_t)(n0 + br) * K6 + bh2 * 8;

    uint2 arh, arl;
    float4 bv0, bv1;
    auto loadS = [&](int kb) {
        arh = *(const uint2*)(fh + kb + aq * 4);
        arl = *(const uint2*)(fl + kb + aq * 4);
        bv0 = *(const float4*)(bp0 + kb);
        bv1 = *(const float4*)(bp0 + kb + 4);
    };

    wmma::fragment<wmma::accumulator, 16, 16, 16, float> c[2][2];
#pragma unroll
    for (int i = 0; i < 2; ++i)
#pragma unroll
        for (int j = 0; j < 2; ++j) wmma::fill_fragment(c[i][j], 0.0f);

    const int kb0 = ks * FC6_KCH;
    loadS(kb0);
    const int NS = FC6_KCH / 16;   // 64
    for (int s = 0; s < NS; ++s) {
        const int buf = s & 1;
        {
            const int da = buf * 1536 + ar * F6STR + aq * 4;
            *(uint2*)&sAh[da] = arh;
            *(uint2*)&sAl[da] = arl;
            __nv_bfloat16 hi[8], lo[8];
            split_bf16(bv0.x, hi[0], lo[0]); split_bf16(bv0.y, hi[1], lo[1]);
            split_bf16(bv0.z, hi[2], lo[2]); split_bf16(bv0.w, hi[3], lo[3]);
            split_bf16(bv1.x, hi[4], lo[4]); split_bf16(bv1.y, hi[5], lo[5]);
            split_bf16(bv1.z, hi[6], lo[6]); split_bf16(bv1.w, hi[7], lo[7]);
            const int db = buf * 3072 + br * F6STR + bh2 * 8;
            *(uint4*)&sBh[db] = *(const uint4*)&hi[0];
            *(uint4*)&sBl[db] = *(const uint4*)&lo[0];
        }
        if (s + 1 < NS) loadS(kb0 + (s + 1) * 16);
        __syncthreads();

        wmma::fragment<wmma::matrix_a, 16, 16, 16, __nv_bfloat16, wmma::row_major> a_hi[2], a_lo[2];
#pragma unroll
        for (int i = 0; i < 2; ++i) {
            wmma::load_matrix_sync(a_hi[i], sAh + buf * 1536 + ((mh * 2 + i) * 16) * F6STR, F6STR);
            wmma::load_matrix_sync(a_lo[i], sAl + buf * 1536 + ((mh * 2 + i) * 16) * F6STR, F6STR);
        }
#pragma unroll
        for (int j = 0; j < 2; ++j) {
            wmma::fragment<wmma::matrix_b, 16, 16, 16, __nv_bfloat16, wmma::col_major> b_hi, b_lo;
            wmma::load_matrix_sync(b_hi, sBh + buf * 3072 + ((nq * 2 + j) * 16) * F6STR, F6STR);
            wmma::load_matrix_sync(b_lo, sBl + buf * 3072 + ((nq * 2 + j) * 16) * F6STR, F6STR);
#pragma unroll
            for (int i = 0; i < 2; ++i) {
                wmma::mma_sync(c[i][j], a_hi[i], b_hi, c[i][j]);
                wmma::mma_sync(c[i][j], a_hi[i], b_lo, c[i][j]);
                wmma::mma_sync(c[i][j], a_lo[i], b_hi, c[i][j]);
            }
        }
        // single barrier per iteration
    }

#pragma unroll
    for (int i = 0; i < 2; ++i)
#pragma unroll
        for (int j = 0; j < 2; ++j) {
            float* p = g_h6p + (size_t)ks * BB * REP + (size_t)((mh * 2 + i) * 16) * REP
                     + n0 + (nq * 2 + j) * 16;
            wmma::store_matrix_sync(p, c[i][j], REP, wmma::mem_row_major);
        }
}

// ---------------------------------------------------------------------------
// Kernel 4: fp32 K-split GEMM for fc7 (unchanged)
// ---------------------------------------------------------------------------
__global__ void __launch_bounds__(256) gemm_nt_partial_fc7(
    const float* __restrict__ Bm, int N, int K, int kchunk) {
    __shared__ float sA[32 * 68];
    __shared__ float sB[32 * 68];

    const float* __restrict__ A = g_h6;
    float* __restrict__ part    = g_outp;

    const int n0 = blockIdx.x * 64;
    const int ks = blockIdx.z;
    const int t = threadIdx.x;
    const int tm = (t >> 4) * 4;
    const int tn = (t & 15) * 4;

    float acc[4][4] = {};

    const int kb0 = ks * kchunk;
    for (int kb = kb0; kb < kb0 + kchunk; kb += 32) {
        for (int i = t; i < 2048; i += 256) {
            const int m = i >> 5, kk = i & 31;
            sA[kk * 68 + m] = A[(size_t)m * K + kb + kk];
        }
        for (int i = t; i < 2048; i += 256) {
            const int n = i >> 5, kk = i & 31;
            sB[kk * 68 + n] = Bm[(size_t)(n0 + n) * K + kb + kk];
        }
        __syncthreads();
#pragma unroll 8
        for (int kk = 0; kk < 32; ++kk) {
            float av[4], bv[4];
#pragma unroll
            for (int j = 0; j < 4; ++j) av[j] = sA[kk * 68 + tm + j];
#pragma unroll
            for (int j = 0; j < 4; ++j) bv[j] = sB[kk * 68 + tn + j];
#pragma unroll
            for (int mi = 0; mi < 4; ++mi)
#pragma unroll
                for (int nj = 0; nj < 4; ++nj)
                    acc[mi][nj] = fmaf(av[mi], bv[nj], acc[mi][nj]);
        }
        __syncthreads();
    }

#pragma unroll
    for (int mi = 0; mi < 4; ++mi)
#pragma unroll
        for (int nj = 0; nj < 4; ++nj)
            part[((size_t)ks * 64 + tm + mi) * N + n0 + tn + nj] = acc[mi][nj];
}

template <int WHICH>
__global__ void fc_reduce_kernel(const float* __restrict__ bias,
                                 float* __restrict__ out_arg) {
    const float* __restrict__ part = (WHICH == 0) ? g_h6p : g_outp;
    float* __restrict__ out        = (WHICH == 0) ? g_h6  : out_arg;
    const int KS                   = (WHICH == 0) ? FC6_KS : FC7_KS;

    const int i = blockIdx.x * 256 + threadIdx.x;
    if (i >= BB * REP) return;
    float s = bias[i & (REP - 1)];
    for (int ks = 0; ks < KS; ++ks)
        s += part[(size_t)ks * BB * REP + i];
    out[i] = fmaxf(s, 0.f);
}

// ---------------------------------------------------------------------------
// Launch
// ---------------------------------------------------------------------------
extern "C" void kernel_launch(void* const* d_in, const int* in_sizes, int n_in,
                              void* d_out, int out_size) {
    const float* x  = (const float*)d_in[0];
    const float* cw = (const float*)d_in[1];
    const float* cb = (const float*)d_in[2];
    const float* w6 = (const float*)d_in[3];
    const float* b6 = (const float*)d_in[4];
    const float* w7 = (const float*)d_in[5];
    const float* b7 = (const float*)d_in[6];
    float* out = (float*)d_out;

    conv_wmma_kernel<<<dim3(CV_KS, BB), 256>>>(x, cw);
    conv_reduce_kernel<<<(BB * COUT * HWHW + 255) / 256, 256>>>(cb);
    einsum_wmma_kernel<<<dim3(CIN / 128, BB), 256>>>(x);
    fc6_wmma_kernel<<<dim3(REP / F6_NB, FC6_KS), 256>>>(w6);
    fc_reduce_kernel<0><<<(BB * REP + 255) / 256, 256>>>(b6, nullptr);
    gemm_nt_partial_fc7<<<dim3(REP / 64, 1, FC7_KS), 256>>>(w7, REP, REP, REP / FC7_KS);
    fc_reduce_kernel<1><<<(BB * REP + 255) / 256, 256>>>(b7, out);
}

// round 12
// speedup vs baseline: 2.2780x; 1.0174x over previous
#include <cuda_runtime.h>
#include <cuda_bf16.h>
#include <cuda_pipeline.h>
#include <mma.h>
#include <cstdint>

using namespace nvcuda;

// ---------------------------------------------------------------------------
// Problem constants
// ---------------------------------------------------------------------------
#define BB    64
#define CIN   2048
#define COUT  32
#define HWHW  196        // 14*14
#define REP   1024
#define K6    (CIN * COUT)   // 65536

#define CV_KS  16                 // conv K-split over channels
#define CV_CPB (CIN / CV_KS)      // 128 channels per block
#define CV_CK  16                 // channels per smem step
#define ILD    24                 // image smem ldm
#define WLD    16                 // weight smem ldm
#define IROWS  272

#define FC6_KS  32                // single wave: 8 * 32 = 256 blocks
#define FC6_KCH (K6 / FC6_KS)     // 2048
#define F6_NB   128               // fc6 N per block
#define F6STR   24                // fc6 smem ldm (k-step 16 + pad 8)
#define FC7_KS  8

#define ELDK    24                // einsum smem ldm

// ---------------------------------------------------------------------------
// Scratch (device globals)
// ---------------------------------------------------------------------------
__device__ float g_am_part[CV_KS * BB * COUT * HWHW];
__device__ float g_am[BB * COUT * HWHW];
__device__ __nv_bfloat16 g_feat_hi[BB * K6];
__device__ __nv_bfloat16 g_feat_lo[BB * K6];
__device__ float g_h6p[FC6_KS * BB * REP];
__device__ float g_h6[BB * REP];
__device__ float g_outp[FC7_KS * BB * REP];

__device__ __forceinline__ void split_bf16(float v, __nv_bfloat16& hi, __nv_bfloat16& lo) {
    hi = __float2bfloat16(v);
    lo = __float2bfloat16(v - __bfloat162float(hi));
}

// ---------------------------------------------------------------------------
// Kernel 1: conv3x3 pad=1 via WMMA bf16 hi/lo (unchanged)
// ---------------------------------------------------------------------------
__global__ void __launch_bounds__(256) conv_wmma_kernel(
    const float* __restrict__ x, const float* __restrict__ w) {
    __shared__ __align__(16) __nv_bfloat16 sIh[IROWS * ILD];
    __shared__ __align__(16) __nv_bfloat16 sIl[IROWS * ILD];
    __shared__ __align__(16) __nv_bfloat16 sWh[9 * 32 * WLD];
    __shared__ __align__(16) __nv_bfloat16 sWl[9 * 32 * WLD];

    const int ks = blockIdx.x, b = blockIdx.y;
    const int t = threadIdx.x;
    const int wid = t >> 5, lane = t & 31;
    const int mg = wid >> 1;
    const int nt = wid & 1;

    for (int i = t; i < IROWS * ILD; i += 256) { sIh[i] = __float2bfloat16(0.f); sIl[i] = sIh[i]; }

    wmma::fragment<wmma::accumulator, 16, 16, 16, float> c[4];
#pragma unroll
    for (int j = 0; j < 4; ++j) wmma::fill_fragment(c[j], 0.0f);

    __syncthreads();

    const int cbase0 = ks * CV_CPB;
    for (int cc = 0; cc < CV_CPB / CV_CK; ++cc) {
        const int cbase = cbase0 + cc * CV_CK;
        for (int i = t; i < CV_CK * HWHW; i += 256) {
            const int cl = i / HWHW, p = i - cl * HWHW;
            const int y = p / 14, xx = p - y * 14;
            const float v = x[((size_t)(b * CIN + cbase + cl)) * HWHW + p];
            const int pos = (y + 1) * 16 + (xx + 1);
            split_bf16(v, sIh[pos * ILD + cl], sIl[pos * ILD + cl]);
        }
        for (int i = t; i < 32 * CV_CK; i += 256) {
            const int o = i >> 4, cl = i & 15;
            const float* wp = w + ((size_t)o * CIN + cbase + cl) * 9;
#pragma unroll
            for (int tap = 0; tap < 9; ++tap)
                split_bf16(wp[tap], sWh[(tap * 32 + o) * WLD + cl],
                                    sWl[(tap * 32 + o) * WLD + cl]);
        }
        __syncthreads();

#pragma unroll
        for (int tap = 0; tap < 9; ++tap) {
            const int dy = tap / 3, dx = tap - dy * 3;
            const int off = dy * 16 + dx;
            wmma::fragment<wmma::matrix_b, 16, 16, 16, __nv_bfloat16, wmma::col_major> b_hi, b_lo;
            wmma::load_matrix_sync(b_hi, sWh + (tap * 32 + nt * 16) * WLD, WLD);
            wmma::load_matrix_sync(b_lo, sWl + (tap * 32 + nt * 16) * WLD, WLD);
#pragma unroll
            for (int j = 0; j < 4; ++j) {
                const int mt = mg * 4 + j;
                if (mt < 14) {
                    wmma::fragment<wmma::matrix_a, 16, 16, 16, __nv_bfloat16, wmma::row_major> a_hi, a_lo;
                    wmma::load_matrix_sync(a_hi, sIh + (mt * 16 + off) * ILD, ILD);
                    wmma::load_matrix_sync(a_lo, sIl + (mt * 16 + off) * ILD, ILD);
                    wmma::mma_sync(c[j], a_hi, b_hi, c[j]);
                    wmma::mma_sync(c[j], a_hi, b_lo, c[j]);
                    wmma::mma_sync(c[j], a_lo, b_hi, c[j]);
                }
            }
        }
        __syncthreads();
    }

    float* stage = reinterpret_cast<float*>(sWh) + wid * 256;
#pragma unroll
    for (int j = 0; j < 4; ++j) {
        const int mt = mg * 4 + j;
        if (mt < 14) {
            wmma::store_matrix_sync(stage, c[j], 16, wmma::mem_row_major);
            __syncwarp();
            for (int e = lane; e < 14 * 16; e += 32) {
                const int row = e >> 4, oc = e & 15;
                g_am_part[(((size_t)ks * BB + b) * COUT + nt * 16 + oc) * HWHW
                          + mt * 14 + row] = stage[row * 16 + oc];
            }
            __syncwarp();
        }
    }
}

__global__ void conv_reduce_kernel(const float* __restrict__ cb) {
    const int i = blockIdx.x * 256 + threadIdx.x;
    if (i >= BB * COUT * HWHW) return;
    const int o = (i / HWHW) & (COUT - 1);
    float s = cb[o];
#pragma unroll
    for (int ks = 0; ks < CV_KS; ++ks)
        s += g_am_part[(size_t)ks * BB * COUT * HWHW + i];
    g_am[i] = s;
}

// ---------------------------------------------------------------------------
// Kernel 2: einsum via WMMA bf16 hi/lo (unchanged from R10)
// ---------------------------------------------------------------------------
__global__ void __launch_bounds__(256) einsum_wmma_kernel(const float* __restrict__ x) {
    __shared__ __align__(16) char esm[30720];
    __nv_bfloat16* sXh  = (__nv_bfloat16*)esm;
    __nv_bfloat16* sXl  = (__nv_bfloat16*)(esm + 12288);
    __nv_bfloat16* sAmh = (__nv_bfloat16*)(esm + 24576);
    __nv_bfloat16* sAml = (__nv_bfloat16*)(esm + 27648);

    const int i0 = blockIdx.x * 128;
    const int b  = blockIdx.y;
    const int t  = threadIdx.x;
    const int wid = t >> 5, lane = t & 31;

    const int xr = t >> 1, xh = t & 1;
    const int ao = t >> 3, aq = t & 7;

    const float* xb = x + ((size_t)(b * CIN + i0 + xr)) * HWHW;
    const float* ab = g_am + ((size_t)b * COUT + ao) * HWHW;

    float4 xv0, xv1;
    float  av0, av1;

    auto loadS = [&](int s) {
        const int k0 = s * 16 + xh * 8;
        xv0 = (k0     < HWHW) ? *(const float4*)(xb + k0)     : make_float4(0,0,0,0);
        xv1 = (k0 + 4 < HWHW) ? *(const float4*)(xb + k0 + 4) : make_float4(0,0,0,0);
        const int ka = s * 16 + aq * 2;
        av0 = (ka     < HWHW) ? ab[ka]     : 0.f;
        av1 = (ka + 1 < HWHW) ? ab[ka + 1] : 0.f;
    };

    wmma::fragment<wmma::accumulator, 16, 16, 16, float> c[2];
    wmma::fill_fragment(c[0], 0.0f);
    wmma::fill_fragment(c[1], 0.0f);

    loadS(0);
    const int NS = 13;
    for (int s = 0; s < NS; ++s) {
        const int buf = s & 1;
        {
            __nv_bfloat16 hi[8], lo[8];
            split_bf16(xv0.x, hi[0], lo[0]); split_bf16(xv0.y, hi[1], lo[1]);
            split_bf16(xv0.z, hi[2], lo[2]); split_bf16(xv0.w, hi[3], lo[3]);
            split_bf16(xv1.x, hi[4], lo[4]); split_bf16(xv1.y, hi[5], lo[5]);
            split_bf16(xv1.z, hi[6], lo[6]); split_bf16(xv1.w, hi[7], lo[7]);
            const int d = buf * 3072 + xr * ELDK + xh * 8;
            *(uint4*)&sXh[d] = *(const uint4*)&hi[0];
            *(uint4*)&sXl[d] = *(const uint4*)&lo[0];
            __nv_bfloat16 ah0, al0, ah1, al1;
            split_bf16(av0, ah0, al0); split_bf16(av1, ah1, al1);
            const int da = buf * 768 + ao * ELDK + aq * 2;
            sAmh[da] = ah0; sAmh[da + 1] = ah1;
            sAml[da] = al0; sAml[da + 1] = al1;
        }
        if (s + 1 < NS) loadS(s + 1);
        __syncthreads();

        wmma::fragment<wmma::matrix_a, 16, 16, 16, __nv_bfloat16, wmma::row_major> a_hi, a_lo;
        wmma::load_matrix_sync(a_hi, sXh + buf * 3072 + (wid * 16) * ELDK, ELDK);
        wmma::load_matrix_sync(a_lo, sXl + buf * 3072 + (wid * 16) * ELDK, ELDK);
#pragma unroll
        for (int j = 0; j < 2; ++j) {
            wmma::fragment<wmma::matrix_b, 16, 16, 16, __nv_bfloat16, wmma::col_major> b_hi, b_lo;
            wmma::load_matrix_sync(b_hi, sAmh + buf * 768 + (j * 16) * ELDK, ELDK);
            wmma::load_matrix_sync(b_lo, sAml + buf * 768 + (j * 16) * ELDK, ELDK);
            wmma::mma_sync(c[j], a_hi, b_hi, c[j]);
            wmma::mma_sync(c[j], a_hi, b_lo, c[j]);
            wmma::mma_sync(c[j], a_lo, b_hi, c[j]);
        }
    }
    __syncthreads();

    float* stage = (float*)esm + wid * 512;
    wmma::store_matrix_sync(stage,      c[0], 32, wmma::mem_row_major);
    wmma::store_matrix_sync(stage + 16, c[1], 32, wmma::mem_row_major);
    __syncwarp();
    const float inv = 1.0f / 196.0f;
    for (int r = 0; r < 16; ++r) {
        const float v = stage[r * 32 + lane] * inv;
        const size_t idx = (size_t)b * K6 + (size_t)(i0 + wid * 16 + r) * COUT + lane;
        split_bf16(v, g_feat_hi[idx], g_feat_lo[idx]);
    }
}

// ---------------------------------------------------------------------------
// Kernel 3: fc6 WMMA. Single wave (grid 8 x 32). A planes via cp.async
// (feat already bf16 in gmem), B split from fp32 with register prefetch.
// Double-buffered, one barrier per k-step of 16.
// ---------------------------------------------------------------------------
__global__ void __launch_bounds__(256) fc6_wmma_kernel(const float* __restrict__ w6) {
    __shared__ __align__(16) char fsm[36864];
    __nv_bfloat16* sAh = (__nv_bfloat16*)fsm;               // [2][64*24]
    __nv_bfloat16* sAl = (__nv_bfloat16*)(fsm + 6144);      // [2][64*24]
    __nv_bfloat16* sBh = (__nv_bfloat16*)(fsm + 12288);     // [2][128*24]
    __nv_bfloat16* sBl = (__nv_bfloat16*)(fsm + 24576);     // [2][128*24]

    const int n0 = blockIdx.x * F6_NB;
    const int ks = blockIdx.y;
    const int t  = threadIdx.x;
    const int wid = t >> 5;
    const int mh  = wid >> 2;      // m-half: tiles {2mh, 2mh+1}
    const int nq  = wid & 3;       // n-quarter: tiles {2nq, 2nq+1}

    const int ar = t >> 2, aq = t & 3;   // A: row 0..63, k-quarter (4 bf16 = 8B)
    const int br = t >> 1, bh2 = t & 1;  // B: row 0..127, k-half (8 fp32)

    const __nv_bfloat16* fh = g_feat_hi + (size_t)ar * K6 + aq * 4;
    const __nv_bfloat16* fl = g_feat_lo + (size_t)ar * K6 + aq * 4;
    const float* bp0 = w6 + (size_t)(n0 + br) * K6 + bh2 * 8;

    const int kb0 = ks * FC6_KCH;
    const int NS = FC6_KCH / 16;   // 128

    auto cpasyncA = [&](int s) {
        const int buf = s & 1;
        const int kb = kb0 + s * 16;
        const int da = buf * 1536 + ar * F6STR + aq * 4;
        __pipeline_memcpy_async(&sAh[da], fh + kb, 8);
        __pipeline_memcpy_async(&sAl[da], fl + kb, 8);
        __pipeline_commit();
    };

    float4 bv0, bv1;
    auto loadB = [&](int s) {
        const int kb = kb0 + s * 16;
        bv0 = *(const float4*)(bp0 + kb);
        bv1 = *(const float4*)(bp0 + kb + 4);
    };

    wmma::fragment<wmma::accumulator, 16, 16, 16, float> c[2][2];
#pragma unroll
    for (int i = 0; i < 2; ++i)
#pragma unroll
        for (int j = 0; j < 2; ++j) wmma::fill_fragment(c[i][j], 0.0f);

    cpasyncA(0);
    loadB(0);

    for (int s = 0; s < NS; ++s) {
        const int buf = s & 1;
        // split + STS B(s) into current buffer
        {
            __nv_bfloat16 hi[8], lo[8];
            split_bf16(bv0.x, hi[0], lo[0]); split_bf16(bv0.y, hi[1], lo[1]);
            split_bf16(bv0.z, hi[2], lo[2]); split_bf16(bv0.w, hi[3], lo[3]);
            split_bf16(bv1.x, hi[4], lo[4]); split_bf16(bv1.y, hi[5], lo[5]);
            split_bf16(bv1.z, hi[6], lo[6]); split_bf16(bv1.w, hi[7], lo[7]);
            const int db = buf * 3072 + br * F6STR + bh2 * 8;
            *(uint4*)&sBh[db] = *(const uint4*)&hi[0];
            *(uint4*)&sBl[db] = *(const uint4*)&lo[0];
        }
        if (s + 1 < NS) loadB(s + 1);     // LDG for next step (latency hidden)
        __pipeline_wait_prior(0);          // A(s) landed (this thread)
        __syncthreads();                   // block-wide: A(s)+B(s) visible, MMA(s-1) done
        if (s + 1 < NS) cpasyncA(s + 1);  // safe: prior readers of alt buffer are done

        wmma::fragment<wmma::matrix_a, 16, 16, 16, __nv_bfloat16, wmma::row_major> a_hi[2], a_lo[2];
#pragma unroll
        for (int i = 0; i < 2; ++i) {
            wmma::load_matrix_sync(a_hi[i], sAh + buf * 1536 + ((mh * 2 + i) * 16) * F6STR, F6STR);
            wmma::load_matrix_sync(a_lo[i], sAl + buf * 1536 + ((mh * 2 + i) * 16) * F6STR, F6STR);
        }
#pragma unroll
        for (int j = 0; j < 2; ++j) {
            wmma::fragment<wmma::matrix_b, 16, 16, 16, __nv_bfloat16, wmma::col_major> b_hi, b_lo;
            wmma::load_matrix_sync(b_hi, sBh + buf * 3072 + ((nq * 2 + j) * 16) * F6STR, F6STR);
            wmma::load_matrix_sync(b_lo, sBl + buf * 3072 + ((nq * 2 + j) * 16) * F6STR, F6STR);
#pragma unroll
            for (int i = 0; i < 2; ++i) {
                wmma::mma_sync(c[i][j], a_hi[i], b_hi, c[i][j]);
                wmma::mma_sync(c[i][j], a_hi[i], b_lo, c[i][j]);
                wmma::mma_sync(c[i][j], a_lo[i], b_hi, c[i][j]);
            }
        }
    }

#pragma unroll
    for (int i = 0; i < 2; ++i)
#pragma unroll
        for (int j = 0; j < 2; ++j) {
            float* p = g_h6p + (size_t)ks * BB * REP + (size_t)((mh * 2 + i) * 16) * REP
                     + n0 + (nq * 2 + j) * 16;
            wmma::store_matrix_sync(p, c[i][j], REP, wmma::mem_row_major);
        }
}

// ---------------------------------------------------------------------------
// Kernel 4: fp32 K-split GEMM for fc7 (unchanged)
// ---------------------------------------------------------------------------
__global__ void __launch_bounds__(256) gemm_nt_partial_fc7(
    const float* __restrict__ Bm, int N, int K, int kchunk) {
    __shared__ float sA[32 * 68];
    __shared__ float sB[32 * 68];

    const float* __restrict__ A = g_h6;
    float* __restrict__ part    = g_outp;

    const int n0 = blockIdx.x * 64;
    const int ks = blockIdx.z;
    const int t = threadIdx.x;
    const int tm = (t >> 4) * 4;
    const int tn = (t & 15) * 4;

    float acc[4][4] = {};

    const int kb0 = ks * kchunk;
    for (int kb = kb0; kb < kb0 + kchunk; kb += 32) {
        for (int i = t; i < 2048; i += 256) {
            const int m = i >> 5, kk = i & 31;
            sA[kk * 68 + m] = A[(size_t)m * K + kb + kk];
        }
        for (int i = t; i < 2048; i += 256) {
            const int n = i >> 5, kk = i & 31;
            sB[kk * 68 + n] = Bm[(size_t)(n0 + n) * K + kb + kk];
        }
        __syncthreads();
#pragma unroll 8
        for (int kk = 0; kk < 32; ++kk) {
            float av[4], bv[4];
#pragma unroll
            for (int j = 0; j < 4; ++j) av[j] = sA[kk * 68 + tm + j];
#pragma unroll
            for (int j = 0; j < 4; ++j) bv[j] = sB[kk * 68 + tn + j];
#pragma unroll
            for (int mi = 0; mi < 4; ++mi)
#pragma unroll
                for (int nj = 0; nj < 4; ++nj)
                    acc[mi][nj] = fmaf(av[mi], bv[nj], acc[mi][nj]);
        }
        __syncthreads();
    }

#pragma unroll
    for (int mi = 0; mi < 4; ++mi)
#pragma unroll
        for (int nj = 0; nj < 4; ++nj)
            part[((size_t)ks * 64 + tm + mi) * N + n0 + tn + nj] = acc[mi][nj];
}

template <int WHICH>
__global__ void fc_reduce_kernel(const float* __restrict__ bias,
                                 float* __restrict__ out_arg) {
    const float* __restrict__ part = (WHICH == 0) ? g_h6p : g_outp;
    float* __restrict__ out        = (WHICH == 0) ? g_h6  : out_arg;
    const int KS                   = (WHICH == 0) ? FC6_KS : FC7_KS;

    const int i = blockIdx.x * 256 + threadIdx.x;
    if (i >= BB * REP) return;
    float s = bias[i & (REP - 1)];
    for (int ks = 0; ks < KS; ++ks)
        s += part[(size_t)ks * BB * REP + i];
    out[i] = fmaxf(s, 0.f);
}

// ---------------------------------------------------------------------------
// Launch
// ---------------------------------------------------------------------------
extern "C" void kernel_launch(void* const* d_in, const int* in_sizes, int n_in,
                              void* d_out, int out_size) {
    const float* x  = (const float*)d_in[0];
    const float* cw = (const float*)d_in[1];
    const float* cb = (const float*)d_in[2];
    const float* w6 = (const float*)d_in[3];
    const float* b6 = (const float*)d_in[4];
    const float* w7 = (const float*)d_in[5];
    const float* b7 = (const float*)d_in[6];
    float* out = (float*)d_out;

    conv_wmma_kernel<<<dim3(CV_KS, BB), 256>>>(x, cw);
    conv_reduce_kernel<<<(BB * COUT * HWHW + 255) / 256, 256>>>(cb);
    einsum_wmma_kernel<<<dim3(CIN / 128, BB), 256>>>(x);
    fc6_wmma_kernel<<<dim3(REP / F6_NB, FC6_KS), 256>>>(w6);
    fc_reduce_kernel<0><<<(BB * REP + 255) / 256, 256>>>(b6, nullptr);
    gemm_nt_partial_fc7<<<dim3(REP / 64, 1, FC7_KS), 256>>>(w7, REP, REP, REP / FC7_KS);
    fc_reduce_kernel<1><<<(BB * REP + 255) / 256, 256>>>(b7, out);
}

// round 15
// speedup vs baseline: 2.3676x; 1.0393x over previous
#include <cuda_runtime.h>
#include <cuda_bf16.h>
#include <cuda_pipeline.h>
#include <mma.h>
#include <cstdint>

using namespace nvcuda;

// ---------------------------------------------------------------------------
// Problem constants
// ---------------------------------------------------------------------------
#define BB    64
#define CIN   2048
#define COUT  32
#define HWHW  196        // 14*14
#define REP   1024
#define K6    (CIN * COUT)   // 65536

#define CV_KS  8                  // conv K-split over channels (halved: less am_part traffic)
#define CV_CPB (CIN / CV_KS)      // 256 channels per block
#define CV_CK  16                 // channels per smem step
#define ILD    24                 // image smem ldm
#define WLD    16                 // weight smem ldm
#define IROWS  272

#define FC6_KS  32                // grid 8 x 32 = 256 blocks (single wave, 2/SM)
#define FC6_KCH (K6 / FC6_KS)     // 2048
#define F6_NB   128               // fc6 N per block
#define FSTR    40                // fc6 smem ldm (k-step 32 + pad 8); 80B rows, 16B-aligned
#define FC7_KS  8

#define ELDK    24                // einsum smem ldm

// ---------------------------------------------------------------------------
// Scratch (device globals)
// ---------------------------------------------------------------------------
__device__ float g_am_part[CV_KS * BB * COUT * HWHW];
__device__ float g_am[BB * COUT * HWHW];
__device__ __nv_bfloat16 g_feat_hi[BB * K6];
__device__ __nv_bfloat16 g_feat_lo[BB * K6];
__device__ float g_h6p[FC6_KS * BB * REP];
__device__ float g_h6[BB * REP];
__device__ float g_outp[FC7_KS * BB * REP];

__device__ __forceinline__ void split_bf16(float v, __nv_bfloat16& hi, __nv_bfloat16& lo) {
    hi = __float2bfloat16(v);
    lo = __float2bfloat16(v - __bfloat162float(hi));
}

// ---------------------------------------------------------------------------
// Kernel 1: conv3x3 pad=1 via WMMA bf16 hi/lo. CV_KS=8 (256 ch/block).
// ---------------------------------------------------------------------------
__global__ void __launch_bounds__(256) conv_wmma_kernel(
    const float* __restrict__ x, const float* __restrict__ w) {
    __shared__ __align__(16) __nv_bfloat16 sIh[IROWS * ILD];
    __shared__ __align__(16) __nv_bfloat16 sIl[IROWS * ILD];
    __shared__ __align__(16) __nv_bfloat16 sWh[9 * 32 * WLD];
    __shared__ __align__(16) __nv_bfloat16 sWl[9 * 32 * WLD];

    const int ks = blockIdx.x, b = blockIdx.y;
    const int t = threadIdx.x;
    const int wid = t >> 5, lane = t & 31;
    const int mg = wid >> 1;
    const int nt = wid & 1;

    for (int i = t; i < IROWS * ILD; i += 256) { sIh[i] = __float2bfloat16(0.f); sIl[i] = sIh[i]; }

    wmma::fragment<wmma::accumulator, 16, 16, 16, float> c[4];
#pragma unroll
    for (int j = 0; j < 4; ++j) wmma::fill_fragment(c[j], 0.0f);

    __syncthreads();

    const int cbase0 = ks * CV_CPB;
    for (int cc = 0; cc < CV_CPB / CV_CK; ++cc) {
        const int cbase = cbase0 + cc * CV_CK;
        for (int i = t; i < CV_CK * HWHW; i += 256) {
            const int cl = i / HWHW, p = i - cl * HWHW;
            const int y = p / 14, xx = p - y * 14;
            const float v = x[((size_t)(b * CIN + cbase + cl)) * HWHW + p];
            const int pos = (y + 1) * 16 + (xx + 1);
            split_bf16(v, sIh[pos * ILD + cl], sIl[pos * ILD + cl]);
        }
        for (int i = t; i < 32 * CV_CK; i += 256) {
            const int o = i >> 4, cl = i & 15;
            const float* wp = w + ((size_t)o * CIN + cbase + cl) * 9;
#pragma unroll
            for (int tap = 0; tap < 9; ++tap)
                split_bf16(wp[tap], sWh[(tap * 32 + o) * WLD + cl],
                                    sWl[(tap * 32 + o) * WLD + cl]);
        }
        __syncthreads();

#pragma unroll
        for (int tap = 0; tap < 9; ++tap) {
            const int dy = tap / 3, dx = tap - dy * 3;
            const int off = dy * 16 + dx;
            wmma::fragment<wmma::matrix_b, 16, 16, 16, __nv_bfloat16, wmma::col_major> b_hi, b_lo;
            wmma::load_matrix_sync(b_hi, sWh + (tap * 32 + nt * 16) * WLD, WLD);
            wmma::load_matrix_sync(b_lo, sWl + (tap * 32 + nt * 16) * WLD, WLD);
#pragma unroll
            for (int j = 0; j < 4; ++j) {
                const int mt = mg * 4 + j;
                if (mt < 14) {
                    wmma::fragment<wmma::matrix_a, 16, 16, 16, __nv_bfloat16, wmma::row_major> a_hi, a_lo;
                    wmma::load_matrix_sync(a_hi, sIh + (mt * 16 + off) * ILD, ILD);
                    wmma::load_matrix_sync(a_lo, sIl + (mt * 16 + off) * ILD, ILD);
                    wmma::mma_sync(c[j], a_hi, b_hi, c[j]);
                    wmma::mma_sync(c[j], a_hi, b_lo, c[j]);
                    wmma::mma_sync(c[j], a_lo, b_hi, c[j]);
                }
            }
        }
        __syncthreads();
    }

    float* stage = reinterpret_cast<float*>(sWh) + wid * 256;
#pragma unroll
    for (int j = 0; j < 4; ++j) {
        const int mt = mg * 4 + j;
        if (mt < 14) {
            wmma::store_matrix_sync(stage, c[j], 16, wmma::mem_row_major);
            __syncwarp();
            for (int e = lane; e < 14 * 16; e += 32) {
                const int row = e >> 4, oc = e & 15;
                g_am_part[(((size_t)ks * BB + b) * COUT + nt * 16 + oc) * HWHW
                          + mt * 14 + row] = stage[row * 16 + oc];
            }
            __syncwarp();
        }
    }
}

__global__ void conv_reduce_kernel(const float* __restrict__ cb) {
    const int i = blockIdx.x * 256 + threadIdx.x;
    if (i >= BB * COUT * HWHW) return;
    const int o = (i / HWHW) & (COUT - 1);
    float s = cb[o];
#pragma unroll
    for (int ks = 0; ks < CV_KS; ++ks)
        s += g_am_part[(size_t)ks * BB * COUT * HWHW + i];
    g_am[i] = s;
}

// ---------------------------------------------------------------------------
// Kernel 2: einsum via WMMA bf16 hi/lo (unchanged)
// ---------------------------------------------------------------------------
__global__ void __launch_bounds__(256) einsum_wmma_kernel(const float* __restrict__ x) {
    __shared__ __align__(16) char esm[30720];
    __nv_bfloat16* sXh  = (__nv_bfloat16*)esm;
    __nv_bfloat16* sXl  = (__nv_bfloat16*)(esm + 12288);
    __nv_bfloat16* sAmh = (__nv_bfloat16*)(esm + 24576);
    __nv_bfloat16* sAml = (__nv_bfloat16*)(esm + 27648);

    const int i0 = blockIdx.x * 128;
    const int b  = blockIdx.y;
    const int t  = threadIdx.x;
    const int wid = t >> 5, lane = t & 31;

    const int xr = t >> 1, xh = t & 1;
    const int ao = t >> 3, aq = t & 7;

    const float* xb = x + ((size_t)(b * CIN + i0 + xr)) * HWHW;
    const float* ab = g_am + ((size_t)b * COUT + ao) * HWHW;

    float4 xv0, xv1;
    float  av0, av1;

    auto loadS = [&](int s) {
        const int k0 = s * 16 + xh * 8;
        xv0 = (k0     < HWHW) ? *(const float4*)(xb + k0)     : make_float4(0,0,0,0);
        xv1 = (k0 + 4 < HWHW) ? *(const float4*)(xb + k0 + 4) : make_float4(0,0,0,0);
        const int ka = s * 16 + aq * 2;
        av0 = (ka     < HWHW) ? ab[ka]     : 0.f;
        av1 = (ka + 1 < HWHW) ? ab[ka + 1] : 0.f;
    };

    wmma::fragment<wmma::accumulator, 16, 16, 16, float> c[2];
    wmma::fill_fragment(c[0], 0.0f);
    wmma::fill_fragment(c[1], 0.0f);

    loadS(0);
    const int NS = 13;
    for (int s = 0; s < NS; ++s) {
        const int buf = s & 1;
        {
            __nv_bfloat16 hi[8], lo[8];
            split_bf16(xv0.x, hi[0], lo[0]); split_bf16(xv0.y, hi[1], lo[1]);
            split_bf16(xv0.z, hi[2], lo[2]); split_bf16(xv0.w, hi[3], lo[3]);
            split_bf16(xv1.x, hi[4], lo[4]); split_bf16(xv1.y, hi[5], lo[5]);
            split_bf16(xv1.z, hi[6], lo[6]); split_bf16(xv1.w, hi[7], lo[7]);
            const int d = buf * 3072 + xr * ELDK + xh * 8;
            *(uint4*)&sXh[d] = *(const uint4*)&hi[0];
            *(uint4*)&sXl[d] = *(const uint4*)&lo[0];
            __nv_bfloat16 ah0, al0, ah1, al1;
            split_bf16(av0, ah0, al0); split_bf16(av1, ah1, al1);
            const int da = buf * 768 + ao * ELDK + aq * 2;
            sAmh[da] = ah0; sAmh[da + 1] = ah1;
            sAml[da] = al0; sAml[da + 1] = al1;
        }
        if (s + 1 < NS) loadS(s + 1);
        __syncthreads();

        wmma::fragment<wmma::matrix_a, 16, 16, 16, __nv_bfloat16, wmma::row_major> a_hi, a_lo;
        wmma::load_matrix_sync(a_hi, sXh + buf * 3072 + (wid * 16) * ELDK, ELDK);
        wmma::load_matrix_sync(a_lo, sXl + buf * 3072 + (wid * 16) * ELDK, ELDK);
#pragma unroll
        for (int j = 0; j < 2; ++j) {
            wmma::fragment<wmma::matrix_b, 16, 16, 16, __nv_bfloat16, wmma::col_major> b_hi, b_lo;
            wmma::load_matrix_sync(b_hi, sAmh + buf * 768 + (j * 16) * ELDK, ELDK);
            wmma::load_matrix_sync(b_lo, sAml + buf * 768 + (j * 16) * ELDK, ELDK);
            wmma::mma_sync(c[j], a_hi, b_hi, c[j]);
            wmma::mma_sync(c[j], a_hi, b_lo, c[j]);
            wmma::mma_sync(c[j], a_lo, b_hi, c[j]);
        }
    }
    __syncthreads();

    float* stage = (float*)esm + wid * 512;
    wmma::store_matrix_sync(stage,      c[0], 32, wmma::mem_row_major);
    wmma::store_matrix_sync(stage + 16, c[1], 32, wmma::mem_row_major);
    __syncwarp();
    const float inv = 1.0f / 196.0f;
    for (int r = 0; r < 16; ++r) {
        const float v = stage[r * 32 + lane] * inv;
        const size_t idx = (size_t)b * K6 + (size_t)(i0 + wid * 16 + r) * COUT + lane;
        split_bf16(v, g_feat_hi[idx], g_feat_lo[idx]);
    }
}

// ---------------------------------------------------------------------------
// Kernel 3: fc6 WMMA. k-step 32, single-wave grid (8 x 32).
// A (feat, pre-split bf16): double-buffered cp.async with 1-group lookahead.
// B (w6 fp32): register prefetch for s+1 issued AFTER sync1 (hides under MMA).
// Single B smem buffer, two barriers per iteration.
// ---------------------------------------------------------------------------
__global__ void __launch_bounds__(256, 2) fc6_wmma_kernel(const float* __restrict__ w6) {
    __shared__ __align__(16) __nv_bfloat16 sAh[2 * 64 * FSTR];   // 10 KB
    __shared__ __align__(16) __nv_bfloat16 sAl[2 * 64 * FSTR];   // 10 KB
    __shared__ __align__(16) __nv_bfloat16 sBh[128 * FSTR];      // 10 KB
    __shared__ __align__(16) __nv_bfloat16 sBl[128 * FSTR];      // 10 KB

    const int n0 = blockIdx.x * F6_NB;
    const int ks = blockIdx.y;
    const int t  = threadIdx.x;
    const int wid = t >> 5;
    const int mh  = wid >> 2;      // m-half: tiles {2mh, 2mh+1}
    const int nq  = wid & 3;       // n-quarter: tiles {2nq, 2nq+1}

    const int ar = t >> 2, aq = t & 3;   // A: row 0..63, k-quarter (8 bf16 = 16B)
    const int br = t >> 1, bh2 = t & 1;  // B: row 0..127, k-half (16 fp32)

    const __nv_bfloat16* fh = g_feat_hi + (size_t)ar * K6 + ks * FC6_KCH + aq * 8;
    const __nv_bfloat16* fl = g_feat_lo + (size_t)ar * K6 + ks * FC6_KCH + aq * 8;
    const float* bp0 = w6 + (size_t)(n0 + br) * K6 + ks * FC6_KCH + bh2 * 16;

    const int NS = FC6_KCH / 32;   // 64

    auto cpasyncA = [&](int s) {
        const int buf = s & 1;
        const int da = buf * (64 * FSTR) + ar * FSTR + aq * 8;
        __pipeline_memcpy_async(&sAh[da], fh + s * 32, 16);
        __pipeline_memcpy_async(&sAl[da], fl + s * 32, 16);
        __pipeline_commit();
    };

    float4 bv[4];
    auto loadB = [&](int s) {
        const float* p = bp0 + s * 32;
#pragma unroll
        for (int j = 0; j < 4; ++j) bv[j] = *(const float4*)(p + j * 4);
    };

    wmma::fragment<wmma::accumulator, 16, 16, 16, float> c[2][2];
#pragma unroll
    for (int i = 0; i < 2; ++i)
#pragma unroll
        for (int j = 0; j < 2; ++j) wmma::fill_fragment(c[i][j], 0.0f);

    cpasyncA(0);
    loadB(0);

    for (int s = 0; s < NS; ++s) {
        const int buf = s & 1;
        // split + STS B(s) (single buffer; previous MMA finished at sync2)
        {
            __nv_bfloat16 hi[16], lo[16];
#pragma unroll
            for (int j = 0; j < 4; ++j) {
                split_bf16(bv[j].x, hi[j * 4 + 0], lo[j * 4 + 0]);
                split_bf16(bv[j].y, hi[j * 4 + 1], lo[j * 4 + 1]);
                split_bf16(bv[j].z, hi[j * 4 + 2], lo[j * 4 + 2]);
                split_bf16(bv[j].w, hi[j * 4 + 3], lo[j * 4 + 3]);
            }
            const int db = br * FSTR + bh2 * 16;
            *(uint4*)&sBh[db + 0] = *(const uint4*)&hi[0];
            *(uint4*)&sBh[db + 8] = *(const uint4*)&hi[8];
            *(uint4*)&sBl[db + 0] = *(const uint4*)&lo[0];
            *(uint4*)&sBl[db + 8] = *(const uint4*)&lo[8];
        }
        if (s + 1 < NS) cpasyncA(s + 1);   // lookahead group in flight
        __pipeline_wait_prior(1);           // A(s) landed; A(s+1) may still fly
        __syncthreads();                    // sync1: A(s)+B(s) visible block-wide
        if (s + 1 < NS) loadB(s + 1);       // LDG hides under MMA below

#pragma unroll
        for (int kk = 0; kk < 2; ++kk) {
            wmma::fragment<wmma::matrix_a, 16, 16, 16, __nv_bfloat16, wmma::row_major> a_hi[2], a_lo[2];
#pragma unroll
            for (int i = 0; i < 2; ++i) {
                const int arow = (mh * 2 + i) * 16;
                wmma::load_matrix_sync(a_hi[i], sAh + buf * (64 * FSTR) + arow * FSTR + kk * 16, FSTR);
                wmma::load_matrix_sync(a_lo[i], sAl + buf * (64 * FSTR) + arow * FSTR + kk * 16, FSTR);
            }
#pragma unroll
            for (int j = 0; j < 2; ++j) {
                const int brow = (nq * 2 + j) * 16;
                wmma::fragment<wmma::matrix_b, 16, 16, 16, __nv_bfloat16, wmma::col_major> b_hi, b_lo;
                wmma::load_matrix_sync(b_hi, sBh + brow * FSTR + kk * 16, FSTR);
                wmma::load_matrix_sync(b_lo, sBl + brow * FSTR + kk * 16, FSTR);
#pragma unroll
                for (int i = 0; i < 2; ++i) {
                    wmma::mma_sync(c[i][j], a_hi[i], b_hi, c[i][j]);
                    wmma::mma_sync(c[i][j], a_hi[i], b_lo, c[i][j]);
                    wmma::mma_sync(c[i][j], a_lo[i], b_hi, c[i][j]);
                }
            }
        }
        __syncthreads();                    // sync2: B buffer free for next STS
    }

#pragma unroll
    for (int i = 0; i < 2; ++i)
#pragma unroll
        for (int j = 0; j < 2; ++j) {
            float* p = g_h6p + (size_t)ks * BB * REP + (size_t)((mh * 2 + i) * 16) * REP
                     + n0 + (nq * 2 + j) * 16;
            wmma::store_matrix_sync(p, c[i][j], REP, wmma::mem_row_major);
        }
}

// ---------------------------------------------------------------------------
// Kernel 4: fp32 K-split GEMM for fc7 (unchanged)
// ---------------------------------------------------------------------------
__global__ void __launch_bounds__(256) gemm_nt_partial_fc7(
    const float* __restrict__ Bm, int N, int K, int kchunk) {
    __shared__ float sA[32 * 68];
    __shared__ float sB[32 * 68];

    const float* __restrict__ A = g_h6;
    float* __restrict__ part    = g_outp;

    const int n0 = blockIdx.x * 64;
    const int ks = blockIdx.z;
    const int t = threadIdx.x;
    const int tm = (t >> 4) * 4;
    const int tn = (t & 15) * 4;

    float acc[4][4] = {};

    const int kb0 = ks * kchunk;
    for (int kb = kb0; kb < kb0 + kchunk; kb += 32) {
        for (int i = t; i < 2048; i += 256) {
            const int m = i >> 5, kk = i & 31;
            sA[kk * 68 + m] = A[(size_t)m * K + kb + kk];
        }
        for (int i = t; i < 2048; i += 256) {
            const int n = i >> 5, kk = i & 31;
            sB[kk * 68 + n] = Bm[(size_t)(n0 + n) * K + kb + kk];
        }
        __syncthreads();
#pragma unroll 8
        for (int kk = 0; kk < 32; ++kk) {
            float av[4], bvv[4];
#pragma unroll
            for (int j = 0; j < 4; ++j) av[j] = sA[kk * 68 + tm + j];
#pragma unroll
            for (int j = 0; j < 4; ++j) bvv[j] = sB[kk * 68 + tn + j];
#pragma unroll
            for (int mi = 0; mi < 4; ++mi)
#pragma unroll
                for (int nj = 0; nj < 4; ++nj)
                    acc[mi][nj] = fmaf(av[mi], bvv[nj], acc[mi][nj]);
        }
        __syncthreads();
    }

#pragma unroll
    for (int mi = 0; mi < 4; ++mi)
#pragma unroll
        for (int nj = 0; nj < 4; ++nj)
            part[((size_t)ks * 64 + tm + mi) * N + n0 + tn + nj] = acc[mi][nj];
}

template <int WHICH>
__global__ void fc_reduce_kernel(const float* __restrict__ bias,
                                 float* __restrict__ out_arg) {
    const float* __restrict__ part = (WHICH == 0) ? g_h6p : g_outp;
    float* __restrict__ out        = (WHICH == 0) ? g_h6  : out_arg;
    const int KS                   = (WHICH == 0) ? FC6_KS : FC7_KS;

    const int i = blockIdx.x * 256 + threadIdx.x;
    if (i >= BB * REP) return;
    float s = bias[i & (REP - 1)];
    for (int ks = 0; ks < KS; ++ks)
        s += part[(size_t)ks * BB * REP + i];
    out[i] = fmaxf(s, 0.f);
}

// ---------------------------------------------------------------------------
// Launch: pure kernel launches.
// ---------------------------------------------------------------------------
extern "C" void kernel_launch(void* const* d_in, const int* in_sizes, int n_in,
                              void* d_out, int out_size) {
    const float* x  = (const float*)d_in[0];
    const float* cw = (const float*)d_in[1];
    const float* cb = (const float*)d_in[2];
    const float* w6 = (const float*)d_in[3];
    const float* b6 = (const float*)d_in[4];
    const float* w7 = (const float*)d_in[5];
    const float* b7 = (const float*)d_in[6];
    float* out = (float*)d_out;

    conv_wmma_kernel<<<dim3(CV_KS, BB), 256>>>(x, cw);
    conv_reduce_kernel<<<(BB * COUT * HWHW + 255) / 256, 256>>>(cb);
    einsum_wmma_kernel<<<dim3(CIN / 128, BB), 256>>>(x);
    fc6_wmma_kernel<<<dim3(REP / F6_NB, FC6_KS), 256>>>(w6);
    fc_reduce_kernel<0><<<(BB * REP + 255) / 256, 256>>>(b6, nullptr);
    gemm_nt_partial_fc7<<<dim3(REP / 64, 1, FC7_KS), 256>>>(w7, REP, REP, REP / FC7_KS);
    fc_reduce_kernel<1><<<(BB * REP + 255) / 256, 256>>>(b7, out);
}

// round 16
// speedup vs baseline: 2.3825x; 1.0063x over previous
#include <cuda_runtime.h>
#include <cuda_bf16.h>
#include <cuda_pipeline.h>
#include <mma.h>
#include <cstdint>

using namespace nvcuda;

// ---------------------------------------------------------------------------
// Problem constants
// ---------------------------------------------------------------------------
#define BB    64
#define CIN   2048
#define COUT  32
#define HWHW  196        // 14*14
#define REP   1024
#define K6    (CIN * COUT)   // 65536

#define CV_KS  4                  // conv K-split: grid 4*64=256 = single wave
#define CV_CPB (CIN / CV_KS)      // 512 channels per block
#define CV_CK  16                 // channels per smem step
#define ILD    24                 // image smem ldm
#define WLD    16                 // weight smem ldm
#define IROWS  272
#define NCHUNK (CIN / CV_CK)      // 128 weight chunks
#define WCHUNK (9 * 32 * CV_CK)   // 4608 bf16 per chunk per plane

#define FC6_KS  32                // grid 8 x 32 = 256 blocks (single wave, 2/SM)
#define FC6_KCH (K6 / FC6_KS)     // 2048
#define F6_NB   128               // fc6 N per block
#define FSTR    40                // fc6 smem ldm
#define FC7_KS  8

#define ELDK    24                // einsum smem ldm

// ---------------------------------------------------------------------------
// Scratch (device globals)
// ---------------------------------------------------------------------------
__device__ float g_am_part[CV_KS * BB * COUT * HWHW];
__device__ float g_am[BB * COUT * HWHW];
__device__ __nv_bfloat16 g_cwh[NCHUNK * WCHUNK];   // pre-split conv weights (hi)
__device__ __nv_bfloat16 g_cwl[NCHUNK * WCHUNK];   // pre-split conv weights (lo)
__device__ __nv_bfloat16 g_feat_hi[BB * K6];
__device__ __nv_bfloat16 g_feat_lo[BB * K6];
__device__ float g_h6p[FC6_KS * BB * REP];
__device__ float g_h6[BB * REP];
__device__ float g_outp[FC7_KS * BB * REP];

__device__ __forceinline__ void split_bf16(float v, __nv_bfloat16& hi, __nv_bfloat16& lo) {
    hi = __float2bfloat16(v);
    lo = __float2bfloat16(v - __bfloat162float(hi));
}

// ---------------------------------------------------------------------------
// Kernel 0 (NEW): pre-split conv weights into smem-order bf16 planes.
// Layout: [chunk][tap][cout][ch16]  (matches conv smem rows exactly)
// ---------------------------------------------------------------------------
__global__ void conv_wsplit_kernel(const float* __restrict__ w) {
    const int i = blockIdx.x * 256 + threadIdx.x;
    if (i >= NCHUNK * WCHUNK) return;
    const int chunk = i / WCHUNK;
    const int r = i - chunk * WCHUNK;
    const int tap = r / (32 * CV_CK);
    const int r2 = r - tap * (32 * CV_CK);
    const int o = r2 >> 4, cl = r2 & 15;
    const int c = chunk * CV_CK + cl;
    split_bf16(w[((size_t)o * CIN + c) * 9 + tap], g_cwh[i], g_cwl[i]);
}

// ---------------------------------------------------------------------------
// Kernel 1: conv3x3 pad=1 via WMMA bf16 hi/lo. CV_KS=4, single wave.
// Weights arrive pre-split: pure uint4 copies into smem.
// ---------------------------------------------------------------------------
__global__ void __launch_bounds__(256) conv_wmma_kernel(const float* __restrict__ x) {
    __shared__ __align__(16) __nv_bfloat16 sIh[IROWS * ILD];
    __shared__ __align__(16) __nv_bfloat16 sIl[IROWS * ILD];
    __shared__ __align__(16) __nv_bfloat16 sWh[9 * 32 * WLD];
    __shared__ __align__(16) __nv_bfloat16 sWl[9 * 32 * WLD];

    const int ks = blockIdx.x, b = blockIdx.y;
    const int t = threadIdx.x;
    const int wid = t >> 5, lane = t & 31;
    const int mg = wid >> 1;
    const int nt = wid & 1;

    for (int i = t; i < IROWS * ILD; i += 256) { sIh[i] = __float2bfloat16(0.f); sIl[i] = sIh[i]; }

    wmma::fragment<wmma::accumulator, 16, 16, 16, float> c[4];
#pragma unroll
    for (int j = 0; j < 4; ++j) wmma::fill_fragment(c[j], 0.0f);

    __syncthreads();

    const int chunk0 = ks * (CV_CPB / CV_CK);
    for (int cc = 0; cc < CV_CPB / CV_CK; ++cc) {
        const int chunk = chunk0 + cc;
        const int cbase = chunk * CV_CK;
        // image: 16 channels x 196 positions (scalar split; halo persists zero)
        for (int i = t; i < CV_CK * HWHW; i += 256) {
            const int cl = i / HWHW, p = i - cl * HWHW;
            const int y = p / 14, xx = p - y * 14;
            const float v = x[((size_t)(b * CIN + cbase + cl)) * HWHW + p];
            const int pos = (y + 1) * 16 + (xx + 1);
            split_bf16(v, sIh[pos * ILD + cl], sIl[pos * ILD + cl]);
        }
        // weights: straight uint4 copies from pre-split planes (576 per plane)
        {
            const uint4* gh = (const uint4*)(g_cwh + (size_t)chunk * WCHUNK);
            const uint4* gl = (const uint4*)(g_cwl + (size_t)chunk * WCHUNK);
            uint4* dh = (uint4*)sWh;
            uint4* dl = (uint4*)sWl;
            for (int i = t; i < WCHUNK / 8; i += 256) { dh[i] = gh[i]; dl[i] = gl[i]; }
        }
        __syncthreads();

#pragma unroll
        for (int tap = 0; tap < 9; ++tap) {
            const int dy = tap / 3, dx = tap - dy * 3;
            const int off = dy * 16 + dx;
            wmma::fragment<wmma::matrix_b, 16, 16, 16, __nv_bfloat16, wmma::col_major> b_hi, b_lo;
            wmma::load_matrix_sync(b_hi, sWh + (tap * 32 + nt * 16) * WLD, WLD);
            wmma::load_matrix_sync(b_lo, sWl + (tap * 32 + nt * 16) * WLD, WLD);
#pragma unroll
            for (int j = 0; j < 4; ++j) {
                const int mt = mg * 4 + j;
                if (mt < 14) {
                    wmma::fragment<wmma::matrix_a, 16, 16, 16, __nv_bfloat16, wmma::row_major> a_hi, a_lo;
                    wmma::load_matrix_sync(a_hi, sIh + (mt * 16 + off) * ILD, ILD);
                    wmma::load_matrix_sync(a_lo, sIl + (mt * 16 + off) * ILD, ILD);
                    wmma::mma_sync(c[j], a_hi, b_hi, c[j]);
                    wmma::mma_sync(c[j], a_hi, b_lo, c[j]);
                    wmma::mma_sync(c[j], a_lo, b_hi, c[j]);
                }
            }
        }
        __syncthreads();
    }

    float* stage = reinterpret_cast<float*>(sWh) + wid * 256;
#pragma unroll
    for (int j = 0; j < 4; ++j) {
        const int mt = mg * 4 + j;
        if (mt < 14) {
            wmma::store_matrix_sync(stage, c[j], 16, wmma::mem_row_major);
            __syncwarp();
            for (int e = lane; e < 14 * 16; e += 32) {
                const int row = e >> 4, oc = e & 15;
                g_am_part[(((size_t)ks * BB + b) * COUT + nt * 16 + oc) * HWHW
                          + mt * 14 + row] = stage[row * 16 + oc];
            }
            __syncwarp();
        }
    }
}

__global__ void conv_reduce_kernel(const float* __restrict__ cb) {
    const int i = blockIdx.x * 256 + threadIdx.x;
    if (i >= BB * COUT * HWHW) return;
    const int o = (i / HWHW) & (COUT - 1);
    float s = cb[o];
#pragma unroll
    for (int ks = 0; ks < CV_KS; ++ks)
        s += g_am_part[(size_t)ks * BB * COUT * HWHW + i];
    g_am[i] = s;
}

// ---------------------------------------------------------------------------
// Kernel 2: einsum via WMMA bf16 hi/lo (unchanged)
// ---------------------------------------------------------------------------
__global__ void __launch_bounds__(256) einsum_wmma_kernel(const float* __restrict__ x) {
    __shared__ __align__(16) char esm[30720];
    __nv_bfloat16* sXh  = (__nv_bfloat16*)esm;
    __nv_bfloat16* sXl  = (__nv_bfloat16*)(esm + 12288);
    __nv_bfloat16* sAmh = (__nv_bfloat16*)(esm + 24576);
    __nv_bfloat16* sAml = (__nv_bfloat16*)(esm + 27648);

    const int i0 = blockIdx.x * 128;
    const int b  = blockIdx.y;
    const int t  = threadIdx.x;
    const int wid = t >> 5, lane = t & 31;

    const int xr = t >> 1, xh = t & 1;
    const int ao = t >> 3, aq = t & 7;

    const float* xb = x + ((size_t)(b * CIN + i0 + xr)) * HWHW;
    const float* ab = g_am + ((size_t)b * COUT + ao) * HWHW;

    float4 xv0, xv1;
    float  av0, av1;

    auto loadS = [&](int s) {
        const int k0 = s * 16 + xh * 8;
        xv0 = (k0     < HWHW) ? *(const float4*)(xb + k0)     : make_float4(0,0,0,0);
        xv1 = (k0 + 4 < HWHW) ? *(const float4*)(xb + k0 + 4) : make_float4(0,0,0,0);
        const int ka = s * 16 + aq * 2;
        av0 = (ka     < HWHW) ? ab[ka]     : 0.f;
        av1 = (ka + 1 < HWHW) ? ab[ka + 1] : 0.f;
    };

    wmma::fragment<wmma::accumulator, 16, 16, 16, float> c[2];
    wmma::fill_fragment(c[0], 0.0f);
    wmma::fill_fragment(c[1], 0.0f);

    loadS(0);
    const int NS = 13;
    for (int s = 0; s < NS; ++s) {
        const int buf = s & 1;
        {
            __nv_bfloat16 hi[8], lo[8];
            split_bf16(xv0.x, hi[0], lo[0]); split_bf16(xv0.y, hi[1], lo[1]);
            split_bf16(xv0.z, hi[2], lo[2]); split_bf16(xv0.w, hi[3], lo[3]);
            split_bf16(xv1.x, hi[4], lo[4]); split_bf16(xv1.y, hi[5], lo[5]);
            split_bf16(xv1.z, hi[6], lo[6]); split_bf16(xv1.w, hi[7], lo[7]);
            const int d = buf * 3072 + xr * ELDK + xh * 8;
            *(uint4*)&sXh[d] = *(const uint4*)&hi[0];
            *(uint4*)&sXl[d] = *(const uint4*)&lo[0];
            __nv_bfloat16 ah0, al0, ah1, al1;
            split_bf16(av0, ah0, al0); split_bf16(av1, ah1, al1);
            const int da = buf * 768 + ao * ELDK + aq * 2;
            sAmh[da] = ah0; sAmh[da + 1] = ah1;
            sAml[da] = al0; sAml[da + 1] = al1;
        }
        if (s + 1 < NS) loadS(s + 1);
        __syncthreads();

        wmma::fragment<wmma::matrix_a, 16, 16, 16, __nv_bfloat16, wmma::row_major> a_hi, a_lo;
        wmma::load_matrix_sync(a_hi, sXh + buf * 3072 + (wid * 16) * ELDK, ELDK);
        wmma::load_matrix_sync(a_lo, sXl + buf * 3072 + (wid * 16) * ELDK, ELDK);
#pragma unroll
        for (int j = 0; j < 2; ++j) {
            wmma::fragment<wmma::matrix_b, 16, 16, 16, __nv_bfloat16, wmma::col_major> b_hi, b_lo;
            wmma::load_matrix_sync(b_hi, sAmh + buf * 768 + (j * 16) * ELDK, ELDK);
            wmma::load_matrix_sync(b_lo, sAml + buf * 768 + (j * 16) * ELDK, ELDK);
            wmma::mma_sync(c[j], a_hi, b_hi, c[j]);
            wmma::mma_sync(c[j], a_hi, b_lo, c[j]);
            wmma::mma_sync(c[j], a_lo, b_hi, c[j]);
        }
    }
    __syncthreads();

    float* stage = (float*)esm + wid * 512;
    wmma::store_matrix_sync(stage,      c[0], 32, wmma::mem_row_major);
    wmma::store_matrix_sync(stage + 16, c[1], 32, wmma::mem_row_major);
    __syncwarp();
    const float inv = 1.0f / 196.0f;
    for (int r = 0; r < 16; ++r) {
        const float v = stage[r * 32 + lane] * inv;
        const size_t idx = (size_t)b * K6 + (size_t)(i0 + wid * 16 + r) * COUT + lane;
        split_bf16(v, g_feat_hi[idx], g_feat_lo[idx]);
    }
}

// ---------------------------------------------------------------------------
// Kernel 3: fc6 WMMA (unchanged from R15: k32, single wave, cp.async lookahead)
// ---------------------------------------------------------------------------
__global__ void __launch_bounds__(256, 2) fc6_wmma_kernel(const float* __restrict__ w6) {
    __shared__ __align__(16) __nv_bfloat16 sAh[2 * 64 * FSTR];
    __shared__ __align__(16) __nv_bfloat16 sAl[2 * 64 * FSTR];
    __shared__ __align__(16) __nv_bfloat16 sBh[128 * FSTR];
    __shared__ __align__(16) __nv_bfloat16 sBl[128 * FSTR];

    const int n0 = blockIdx.x * F6_NB;
    const int ks = blockIdx.y;
    const int t  = threadIdx.x;
    const int wid = t >> 5;
    const int mh  = wid >> 2;
    const int nq  = wid & 3;

    const int ar = t >> 2, aq = t & 3;
    const int br = t >> 1, bh2 = t & 1;

    const __nv_bfloat16* fh = g_feat_hi + (size_t)ar * K6 + ks * FC6_KCH + aq * 8;
    const __nv_bfloat16* fl = g_feat_lo + (size_t)ar * K6 + ks * FC6_KCH + aq * 8;
    const float* bp0 = w6 + (size_t)(n0 + br) * K6 + ks * FC6_KCH + bh2 * 16;

    const int NS = FC6_KCH / 32;   // 64

    auto cpasyncA = [&](int s) {
        const int buf = s & 1;
        const int da = buf * (64 * FSTR) + ar * FSTR + aq * 8;
        __pipeline_memcpy_async(&sAh[da], fh + s * 32, 16);
        __pipeline_memcpy_async(&sAl[da], fl + s * 32, 16);
        __pipeline_commit();
    };

    float4 bv[4];
    auto loadB = [&](int s) {
        const float* p = bp0 + s * 32;
#pragma unroll
        for (int j = 0; j < 4; ++j) bv[j] = *(const float4*)(p + j * 4);
    };

    wmma::fragment<wmma::accumulator, 16, 16, 16, float> c[2][2];
#pragma unroll
    for (int i = 0; i < 2; ++i)
#pragma unroll
        for (int j = 0; j < 2; ++j) wmma::fill_fragment(c[i][j], 0.0f);

    cpasyncA(0);
    loadB(0);

    for (int s = 0; s < NS; ++s) {
        const int buf = s & 1;
        {
            __nv_bfloat16 hi[16], lo[16];
#pragma unroll
            for (int j = 0; j < 4; ++j) {
                split_bf16(bv[j].x, hi[j * 4 + 0], lo[j * 4 + 0]);
                split_bf16(bv[j].y, hi[j * 4 + 1], lo[j * 4 + 1]);
                split_bf16(bv[j].z, hi[j * 4 + 2], lo[j * 4 + 2]);
                split_bf16(bv[j].w, hi[j * 4 + 3], lo[j * 4 + 3]);
            }
            const int db = br * FSTR + bh2 * 16;
            *(uint4*)&sBh[db + 0] = *(const uint4*)&hi[0];
            *(uint4*)&sBh[db + 8] = *(const uint4*)&hi[8];
            *(uint4*)&sBl[db + 0] = *(const uint4*)&lo[0];
            *(uint4*)&sBl[db + 8] = *(const uint4*)&lo[8];
        }
        if (s + 1 < NS) cpasyncA(s + 1);
        __pipeline_wait_prior(1);
        __syncthreads();
        if (s + 1 < NS) loadB(s + 1);

#pragma unroll
        for (int kk = 0; kk < 2; ++kk) {
            wmma::fragment<wmma::matrix_a, 16, 16, 16, __nv_bfloat16, wmma::row_major> a_hi[2], a_lo[2];
#pragma unroll
            for (int i = 0; i < 2; ++i) {
                const int arow = (mh * 2 + i) * 16;
                wmma::load_matrix_sync(a_hi[i], sAh + buf * (64 * FSTR) + arow * FSTR + kk * 16, FSTR);
                wmma::load_matrix_sync(a_lo[i], sAl + buf * (64 * FSTR) + arow * FSTR + kk * 16, FSTR);
            }
#pragma unroll
            for (int j = 0; j < 2; ++j) {
                const int brow = (nq * 2 + j) * 16;
                wmma::fragment<wmma::matrix_b, 16, 16, 16, __nv_bfloat16, wmma::col_major> b_hi, b_lo;
                wmma::load_matrix_sync(b_hi, sBh + brow * FSTR + kk * 16, FSTR);
                wmma::load_matrix_sync(b_lo, sBl + brow * FSTR + kk * 16, FSTR);
#pragma unroll
                for (int i = 0; i < 2; ++i) {
                    wmma::mma_sync(c[i][j], a_hi[i], b_hi, c[i][j]);
                    wmma::mma_sync(c[i][j], a_hi[i], b_lo, c[i][j]);
                    wmma::mma_sync(c[i][j], a_lo[i], b_hi, c[i][j]);
                }
            }
        }
        __syncthreads();
    }

#pragma unroll
    for (int i = 0; i < 2; ++i)
#pragma unroll
        for (int j = 0; j < 2; ++j) {
            float* p = g_h6p + (size_t)ks * BB * REP + (size_t)((mh * 2 + i) * 16) * REP
                     + n0 + (nq * 2 + j) * 16;
            wmma::store_matrix_sync(p, c[i][j], REP, wmma::mem_row_major);
        }
}

// ---------------------------------------------------------------------------
// Kernel 4: fp32 K-split GEMM for fc7 (unchanged)
// ---------------------------------------------------------------------------
__global__ void __launch_bounds__(256) gemm_nt_partial_fc7(
    const float* __restrict__ Bm, int N, int K, int kchunk) {
    __shared__ float sA[32 * 68];
    __shared__ float sB[32 * 68];

    const float* __restrict__ A = g_h6;
    float* __restrict__ part    = g_outp;

    const int n0 = blockIdx.x * 64;
    const int ks = blockIdx.z;
    const int t = threadIdx.x;
    const int tm = (t >> 4) * 4;
    const int tn = (t & 15) * 4;

    float acc[4][4] = {};

    const int kb0 = ks * kchunk;
    for (int kb = kb0; kb < kb0 + kchunk; kb += 32) {
        for (int i = t; i < 2048; i += 256) {
            const int m = i >> 5, kk = i & 31;
            sA[kk * 68 + m] = A[(size_t)m * K + kb + kk];
        }
        for (int i = t; i < 2048; i += 256) {
            const int n = i >> 5, kk = i & 31;
            sB[kk * 68 + n] = Bm[(size_t)(n0 + n) * K + kb + kk];
        }
        __syncthreads();
#pragma unroll 8
        for (int kk = 0; kk < 32; ++kk) {
            float av[4], bvv[4];
#pragma unroll
            for (int j = 0; j < 4; ++j) av[j] = sA[kk * 68 + tm + j];
#pragma unroll
            for (int j = 0; j < 4; ++j) bvv[j] = sB[kk * 68 + tn + j];
#pragma unroll
            for (int mi = 0; mi < 4; ++mi)
#pragma unroll
                for (int nj = 0; nj < 4; ++nj)
                    acc[mi][nj] = fmaf(av[mi], bvv[nj], acc[mi][nj]);
        }
        __syncthreads();
    }

#pragma unroll
    for (int mi = 0; mi < 4; ++mi)
#pragma unroll
        for (int nj = 0; nj < 4; ++nj)
            part[((size_t)ks * 64 + tm + mi) * N + n0 + tn + nj] = acc[mi][nj];
}

template <int WHICH>
__global__ void fc_reduce_kernel(const float* __restrict__ bias,
                                 float* __restrict__ out_arg) {
    const float* __restrict__ part = (WHICH == 0) ? g_h6p : g_outp;
    float* __restrict__ out        = (WHICH == 0) ? g_h6  : out_arg;
    const int KS                   = (WHICH == 0) ? FC6_KS : FC7_KS;

    const int i = blockIdx.x * 256 + threadIdx.x;
    if (i >= BB * REP) return;
    float s = bias[i & (REP - 1)];
    for (int ks = 0; ks < KS; ++ks)
        s += part[(size_t)ks * BB * REP + i];
    out[i] = fmaxf(s, 0.f);
}

// ---------------------------------------------------------------------------
// Launch: pure kernel launches.
// ---------------------------------------------------------------------------
extern "C" void kernel_launch(void* const* d_in, const int* in_sizes, int n_in,
                              void* d_out, int out_size) {
    const float* x  = (const float*)d_in[0];
    const float* cw = (const float*)d_in[1];
    const float* cb = (const float*)d_in[2];
    const float* w6 = (const float*)d_in[3];
    const float* b6 = (const float*)d_in[4];
    const float* w7 = (const float*)d_in[5];
    const float* b7 = (const float*)d_in[6];
    float* out = (float*)d_out;

    conv_wsplit_kernel<<<(NCHUNK * WCHUNK + 255) / 256, 256>>>(cw);
    conv_wmma_kernel<<<dim3(CV_KS, BB), 256>>>(x);
    conv_reduce_kernel<<<(BB * COUT * HWHW + 255) / 256, 256>>>(cb);
    einsum_wmma_kernel<<<dim3(CIN / 128, BB), 256>>>(x);
    fc6_wmma_kernel<<<dim3(REP / F6_NB, FC6_KS), 256>>>(w6);
    fc_reduce_kernel<0><<<(BB * REP + 255) / 256, 256>>>(b6, nullptr);
    gemm_nt_partial_fc7<<<dim3(REP / 64, 1, FC7_KS), 256>>>(w7, REP, REP, REP / FC7_KS);
    fc_reduce_kernel<1><<<(BB * REP + 255) / 256, 256>>>(b7, out);
}